// round 3
// baseline (speedup 1.0000x reference)
#include <cuda_runtime.h>
#include <math.h>

#define Bn 8
#define Cc 64
#define Hh 256
#define Ww 256
#define Ll 4
#define M1 20
#define M2 20
#define BC (Bn*Cc)          // 512
#define HW (Hh*Ww)          // 65536
#define NPIX (Bn*HW)        // 524288
#define NTOT (BC*HW)        // 33554432

// ---------------- scratch (device globals; no allocations allowed) ----------
__device__ float g_h0[NTOT];                 // ping
__device__ float g_h1[NTOT];                 // pong
__device__ float g_xf[BC*Hh*M2*2];           // fwd-x result (bc,y,kx) complex
__device__ float g_F [BC*2*M1*M2*2];         // fwd-y result (bc,kyi,kx) complex
__device__ float g_D [BC*2*M1*M2*2];         // after channel mix
__device__ float g_gy[BC*Hh*M2*2];           // inv-y result (bc,y,kx) complex, pre-scaled
__device__ float g_wt[Ll*Cc*9*Cc];           // combined conv weights [l][ci][tap][co]
__device__ float g_bc2[Ll*Cc];               // combined conv bias
__device__ float g_cx[M2*Hh];                // cos(2pi k x/256), [k][x]
__device__ float g_sx[M2*Hh];                // sin(2pi k x/256), [k][x]
__device__ float g_cy[Hh*2*M1];              // [y][kyi], ky = kyi<20?kyi:216+kyi
__device__ float g_sy[Hh*2*M1];

// ---------------- prep: fold convh+convw+pw into one 3x3 conv ---------------
__global__ void k_prep_w(const float* __restrict__ ch, const float* __restrict__ cw,
                         const float* __restrict__ pw, const float* __restrict__ bh,
                         const float* __restrict__ bw, const float* __restrict__ bp)
{
    int idx = blockIdx.x*blockDim.x + threadIdx.x;
    int total = Ll*Cc*Cc*9;
    if (idx < total) {
        // destination layout: [l][ci][tap][co]  (co fastest for LDS.128 in conv)
        int co  = idx & 63;
        int tap = (idx >> 6) % 9;
        int ci  = (idx / (64*9)) & 63;
        int l   = idx / (64*9*64);
        int src = ((l*64 + co)*64 + ci)*9 + tap;       // source: (L,O,I,3,3)
        float v = ch[src] + cw[src];
        if (tap == 4) v += pw[(l*64 + co)*64 + ci];    // 1x1 folded into center
        g_wt[idx] = v;
    }
    if (idx < Ll*Cc) g_bc2[idx] = bh[idx] + bw[idx] + bp[idx];
}

__global__ void k_prep_trig()
{
    int idx = blockIdx.x*blockDim.x + threadIdx.x;
    if (idx < M2*Hh) {                                  // [k][x]
        int k = idx >> 8, x = idx & 255;
        int m = (k*x) & 255;                            // exact angle reduction
        double t = (double)m * (6.283185307179586476925287 / 256.0);
        double s, c; sincos(t, &s, &c);
        g_cx[idx] = (float)c; g_sx[idx] = (float)s;
    }
    if (idx < Hh*2*M1) {                                // [y][kyi]
        int y = idx / 40, kyi = idx % 40;
        int ky = (kyi < 20) ? kyi : (216 + kyi);        // 236..255
        int m = (ky*y) & 255;
        double t = (double)m * (6.283185307179586476925287 / 256.0);
        double s, c; sincos(t, &s, &c);
        g_cy[idx] = (float)c; g_sy[idx] = (float)s;
    }
}

// ---------------- fc0 lift: (B,H,W,3) -> (B,C,H,W) --------------------------
__global__ void k_fc0(const float* __restrict__ xin, const float* __restrict__ w,
                      const float* __restrict__ b)
{
    int idx = blockIdx.x*blockDim.x + threadIdx.x;
    if (idx >= NTOT) return;
    int x  = idx & 255;
    int y  = (idx >> 8) & 255;
    int c  = (idx >> 16) & 63;
    int bb = idx >> 22;
    const float* xp = xin + ((size_t)(bb*Hh + y)*Ww + x)*3;
    float v = __ldg(&b[c]) + xp[0]*__ldg(&w[c]) + xp[1]*__ldg(&w[64+c]) + xp[2]*__ldg(&w[128+c]);
    g_h0[idx] = v;
}

// ---------------- combined 3x3 conv (NCHW), tile 32x8, all 64 co ------------
__global__ __launch_bounds__(256) void k_conv(int l, int sel)
{
    const float* hin = sel ? g_h1 : g_h0;
    float*      hout = sel ? g_h0 : g_h1;

    __shared__ float s_in[8][10][34];
    __shared__ float s_w[8*9*64];
    __shared__ float s_b[64];

    int t  = threadIdx.x;
    int px = t & 31, py = t >> 5;
    int x0 = blockIdx.x * 32;
    int y0 = blockIdx.y * 8;
    int b  = blockIdx.z;
    if (t < 64) s_b[t] = g_bc2[l*64 + t];

    float acc[64];
#pragma unroll
    for (int i = 0; i < 64; i++) acc[i] = 0.f;

    const float* hb = hin + (size_t)b*Cc*HW;
    for (int cc = 0; cc < 8; cc++) {
        __syncthreads();
        // input tile (8 ci) x (10 y) x (34 x) with zero halo
        for (int e = t; e < 8*10*34; e += 256) {
            int ci = e / 340;
            int r  = e % 340;
            int dy = r / 34, dx = r % 34;
            int gy = y0 + dy - 1, gx = x0 + dx - 1;
            float v = 0.f;
            if (gy >= 0 && gy < 256 && gx >= 0 && gx < 256)
                v = hb[(size_t)(cc*8 + ci)*HW + gy*256 + gx];
            s_in[ci][dy][dx] = v;
        }
        // weight chunk: contiguous [ci8][tap][co]
        int wbase = ((l*64 + cc*8)*9)*64;
        for (int e = t; e < 8*9*64; e += 256) s_w[e] = g_wt[wbase + e];
        __syncthreads();

#pragma unroll
        for (int ci = 0; ci < 8; ci++) {
            float v[9];
#pragma unroll
            for (int fy = 0; fy < 3; fy++)
#pragma unroll
                for (int fx = 0; fx < 3; fx++)
                    v[fy*3+fx] = s_in[ci][py+fy][px+fx];
#pragma unroll
            for (int tap = 0; tap < 9; tap++) {
                const float4* wp = (const float4*)&s_w[(ci*9 + tap)*64];
                float vt = v[tap];
#pragma unroll
                for (int j = 0; j < 16; j++) {
                    float4 w4 = wp[j];
                    acc[4*j+0] += vt*w4.x;
                    acc[4*j+1] += vt*w4.y;
                    acc[4*j+2] += vt*w4.z;
                    acc[4*j+3] += vt*w4.w;
                }
            }
        }
    }
    float* ob = hout + (size_t)b*Cc*HW + (size_t)(y0+py)*256 + (x0+px);
#pragma unroll
    for (int co = 0; co < 64; co++) ob[(size_t)co*HW] = acc[co] + s_b[co];
}

// ---------------- forward partial DFT along x: 20 modes ---------------------
__global__ __launch_bounds__(512) void k_fwdx(int sel)
{
    const float* hin = sel ? g_h1 : g_h0;
    __shared__ float sc[M2*Hh];
    __shared__ float ss[M2*Hh];
    int t = threadIdx.x;
    for (int e = t; e < M2*Hh; e += 512) { sc[e] = g_cx[e]; ss[e] = g_sx[e]; }
    __syncthreads();

    int warp = t >> 5, lane = t & 31;
    int row = blockIdx.x * 16 + warp;                 // row in [0, BC*Hh)
    const float* rp = hin + (size_t)row * 256;
    float v[8];
#pragma unroll
    for (int j = 0; j < 8; j++) v[j] = rp[lane + 32*j];

    float* outp = g_xf + (size_t)row * (M2*2);
    for (int k = 0; k < 20; k++) {
        float ar = 0.f, ai = 0.f;
#pragma unroll
        for (int j = 0; j < 8; j++) {
            int x = lane + 32*j;
            float c = sc[k*256 + x], s = ss[k*256 + x];
            ar += v[j]*c;
            ai -= v[j]*s;
        }
#pragma unroll
        for (int o = 16; o > 0; o >>= 1) {
            ar += __shfl_xor_sync(0xffffffffu, ar, o);
            ai += __shfl_xor_sync(0xffffffffu, ai, o);
        }
        if (lane == 0) { outp[2*k] = ar*0.0625f; outp[2*k+1] = ai*0.0625f; }
    }
}

// ---------------- forward partial DFT along y: 40 modes (0..19, 236..255) ---
__global__ __launch_bounds__(800) void k_fwdy()
{
    __shared__ float sX[Hh*M2*2];                     // 40KB slab for this image
    int bc = blockIdx.x;
    int t  = threadIdx.x;
    const float* src = g_xf + (size_t)bc * (Hh*M2*2);
    for (int e = t; e < Hh*M2*2; e += 800) sX[e] = src[e];
    __syncthreads();

    int kx = t % 20, kyi = t / 20;                    // kyi in [0,40)
    float ar = 0.f, ai = 0.f;
#pragma unroll 4
    for (int y = 0; y < 256; y++) {
        float xr = sX[(y*20 + kx)*2], xi = sX[(y*20 + kx)*2 + 1];
        float c = __ldg(&g_cy[y*40 + kyi]), s = __ldg(&g_sy[y*40 + kyi]);
        ar += xr*c + xi*s;                            // X * e^{-i th}
        ai += xi*c - xr*s;
    }
    size_t o = ((size_t)(bc*40 + kyi)*20 + kx)*2;
    g_F[o]   = ar*0.0625f;
    g_F[o+1] = ai*0.0625f;
}

// ---------------- per-mode 64x64 complex channel mix ------------------------
__global__ __launch_bounds__(512) void k_mix(const float* __restrict__ w1,
                                             const float* __restrict__ w2, int l)
{
    __shared__ float sW[Cc*Cc*2];                     // [i][o] complex, 32KB
    __shared__ float sF[Bn*Cc*2];                     // [b][i] complex, 4KB
    int m   = blockIdx.x;                             // 0..799
    int kyi = m / 20, kx = m % 20;
    const float* wsrc = (kyi < 20) ? w1 : w2;
    int kk = (kyi < 20) ? kyi : (kyi - 20);
    int t = threadIdx.x;

    for (int e = t; e < Cc*Cc; e += 512) {
        int i = e >> 6, o = e & 63;
        size_t s = ((((size_t)(l*64 + i)*64 + o)*20 + kk)*20 + kx)*2;
        sW[e*2]   = wsrc[s];
        sW[e*2+1] = wsrc[s+1];
    }
    {
        int e = t;                                    // e = b*64+i  (512 threads)
        size_t s = (((size_t)e*40 + kyi)*20 + kx)*2;
        sF[e*2]   = g_F[s];
        sF[e*2+1] = g_F[s+1];
    }
    __syncthreads();

    int o = t & 63, b = t >> 6;
    float ar = 0.f, ai = 0.f;
#pragma unroll 4
    for (int i = 0; i < 64; i++) {
        float fr = sF[(b*64 + i)*2], fi = sF[(b*64 + i)*2 + 1];
        float wr = sW[(i*64 + o)*2], wi = sW[(i*64 + o)*2 + 1];
        ar += fr*wr - fi*wi;
        ai += fr*wi + fi*wr;
    }
    size_t d = (((size_t)(b*64 + o)*40 + kyi)*20 + kx)*2;
    g_D[d] = ar; g_D[d+1] = ai;
}

// ---------------- inverse DFT along y (pre-scales for inv-x) ----------------
__global__ __launch_bounds__(640) void k_invy()
{
    __shared__ float sD[2*M1*M2*2];                   // 1600 floats
    int bc = blockIdx.x;
    int t  = threadIdx.x;
    const float* src = g_D + (size_t)bc*2*M1*M2*2;
    for (int e = t; e < 2*M1*M2*2; e += 640) sD[e] = src[e];
    __syncthreads();

    int kx = t % 20, yb = t / 20;                     // yb in [0,32)
    float scale = (kx == 0) ? (1.0f/256.0f) : (2.0f/256.0f);
    for (int jj = 0; jj < 8; jj++) {
        int y = yb + 32*jj;
        float ar = 0.f, ai = 0.f;
#pragma unroll 8
        for (int kyi = 0; kyi < 40; kyi++) {
            float dr = sD[(kyi*20 + kx)*2], di = sD[(kyi*20 + kx)*2 + 1];
            float c = __ldg(&g_cy[y*40 + kyi]), s = __ldg(&g_sy[y*40 + kyi]);
            ar += dr*c - di*s;                        // D * e^{+i th}
            ai += dr*s + di*c;
        }
        size_t o = ((size_t)(bc*256 + y)*20 + kx)*2;
        g_gy[o] = ar*scale; g_gy[o+1] = ai*scale;
    }
}

// ---------------- inverse DFT along x + add conv + GeLU ---------------------
__global__ __launch_bounds__(512) void k_invx(int sel, int do_gelu)
{
    float* hout = sel ? g_h0 : g_h1;                  // conv output buffer
    __shared__ float sc[M2*Hh];
    __shared__ float ss[M2*Hh];
    __shared__ float sg[16][40];
    int t = threadIdx.x;
    for (int e = t; e < M2*Hh; e += 512) { sc[e] = g_cx[e]; ss[e] = g_sx[e]; }

    int bc = blockIdx.x;
    int y0 = blockIdx.y * 16;
    for (int e = t; e < 16*40; e += 512) {
        int r = e / 40, q = e % 40;
        sg[r][q] = g_gy[((size_t)(bc*256 + y0 + r))*40 + q];
    }
    __syncthreads();

    int x = t & 255, r0 = t >> 8;                     // r0 in {0,1}
    for (int it = 0; it < 8; it++) {
        int r = r0 + 2*it;
        float val = sg[r][0];                         // kx=0: Re only (C2R semantics)
#pragma unroll
        for (int k = 1; k < 20; k++) {
            float gr = sg[r][2*k], gi = sg[r][2*k+1];
            val += gr*sc[k*256 + x] - gi*ss[k*256 + x];
        }
        size_t idx = ((size_t)(bc*256 + y0 + r))*256 + x;
        float h = hout[idx] + val;
        if (do_gelu) h = 0.5f*h*(1.0f + erff(h*0.70710678118654752440f));
        hout[idx] = h;
    }
}

// ---------------- head: fc1 + gelu + fc2 ------------------------------------
__global__ __launch_bounds__(256) void k_head(const float* __restrict__ w1,
                                              const float* __restrict__ b1,
                                              const float* __restrict__ w2,
                                              const float* __restrict__ b2,
                                              float* __restrict__ out)
{
    __shared__ float sw1[64*128];
    __shared__ float sb1[128];
    __shared__ float sw2[128];
    int t = threadIdx.x;
    for (int e = t; e < 64*128; e += 256) sw1[e] = w1[e];
    if (t < 128) { sb1[t] = b1[t]; sw2[t] = w2[t]; }
    __syncthreads();

    int pix = blockIdx.x * 256 + t;                   // over NPIX
    int x = pix & 255, y = (pix >> 8) & 255, b = pix >> 16;
    const float* hp = g_h0 + (size_t)b*64*HW + (size_t)y*256 + x;  // final h in g_h0

    float o = __ldg(&b2[0]);
    for (int half = 0; half < 2; half++) {
        float acc[64];
#pragma unroll
        for (int d = 0; d < 64; d++) acc[d] = sb1[half*64 + d];
#pragma unroll 4
        for (int c = 0; c < 64; c++) {
            float v = __ldg(&hp[(size_t)c*HW]);
            const float4* wp = (const float4*)&sw1[c*128 + half*64];
#pragma unroll
            for (int j = 0; j < 16; j++) {
                float4 w4 = wp[j];
                acc[4*j+0] += v*w4.x;
                acc[4*j+1] += v*w4.y;
                acc[4*j+2] += v*w4.z;
                acc[4*j+3] += v*w4.w;
            }
        }
#pragma unroll
        for (int d = 0; d < 64; d++) {
            float tt = acc[d];
            tt = 0.5f*tt*(1.0f + erff(tt*0.70710678118654752440f));
            o += tt * sw2[half*64 + d];
        }
    }
    out[pix] = o;
}

// ---------------- launch -----------------------------------------------------
extern "C" void kernel_launch(void* const* d_in, const int* in_sizes, int n_in,
                              void* d_out, int out_size)
{
    const float* x    = (const float*)d_in[0];
    const float* fc0w = (const float*)d_in[1];
    const float* fc0b = (const float*)d_in[2];
    const float* w1   = (const float*)d_in[3];
    const float* w2   = (const float*)d_in[4];
    const float* chw  = (const float*)d_in[5];
    const float* chb  = (const float*)d_in[6];
    const float* cww  = (const float*)d_in[7];
    const float* cwb  = (const float*)d_in[8];
    const float* pww  = (const float*)d_in[9];
    const float* pwb  = (const float*)d_in[10];
    const float* f1w  = (const float*)d_in[11];
    const float* f1b  = (const float*)d_in[12];
    const float* f2w  = (const float*)d_in[13];
    const float* f2b  = (const float*)d_in[14];
    float* out = (float*)d_out;
    (void)in_sizes; (void)n_in; (void)out_size;

    k_prep_w<<<(Ll*Cc*Cc*9 + 255)/256, 256>>>(chw, cww, pww, chb, cwb, pwb);
    k_prep_trig<<<40, 256>>>();
    k_fc0<<<NTOT/256, 256>>>(x, fc0w, fc0b);

    for (int l = 0; l < Ll; l++) {
        int sel = l & 1;                              // 0: h0->h1, 1: h1->h0
        k_conv<<<dim3(8, 32, 8), 256>>>(l, sel);
        k_fwdx<<<BC*Hh/16, 512>>>(sel);
        k_fwdy<<<BC, 800>>>();
        k_mix<<<800, 512>>>(w1, w2, l);
        k_invy<<<BC, 640>>>();
        k_invx<<<dim3(BC, 16), 512>>>(sel, (l < Ll-1) ? 1 : 0);
    }
    // after 4 layers (even count), final h is in g_h0
    k_head<<<NPIX/256, 256>>>(f1w, f1b, f2w, f2b, out);
}

// round 7
// speedup vs baseline: 1.1707x; 1.1707x over previous
#include <cuda_runtime.h>
#include <math.h>

#define Bn 8
#define Cc 64
#define Hh 256
#define Ww 256
#define Ll 4
#define M1 20
#define M2 20
#define BC (Bn*Cc)          // 512
#define HW (Hh*Ww)          // 65536
#define NPIX (Bn*HW)        // 524288
#define NTOT (BC*HW)        // 33554432

// ---------------- scratch (device globals; no allocations allowed) ----------
__device__ float g_h0[NTOT];                 // ping
__device__ float g_h1[NTOT];                 // pong
__device__ float g_xf[BC*Hh*M2*2];           // fwd-x result (bc,y,kx) complex
__device__ float g_F [BC*2*M1*M2*2];         // fwd-y result (bc,kyi,kx) complex
__device__ float g_D [BC*2*M1*M2*2];         // after channel mix
__device__ float g_gy[BC*Hh*M2*2];           // inv-y result (bc,y,kx) complex, pre-scaled
__device__ float g_wt[Ll*Cc*9*Cc];           // combined conv weights [l][ci][tap][co]
__device__ float g_bc2[Ll*Cc];               // combined conv bias
__device__ float g_cx[M2*Hh];                // cos(2pi k x/256), [k][x]
__device__ float g_sx[M2*Hh];                // sin(2pi k x/256), [k][x]
__device__ float g_cy[Hh*2*M1];              // [y][kyi], ky = kyi<20?kyi:216+kyi
__device__ float g_sy[Hh*2*M1];

// ---------------- prep: fold convh+convw+pw into one 3x3 conv ---------------
__global__ void k_prep_w(const float* __restrict__ ch, const float* __restrict__ cw,
                         const float* __restrict__ pw, const float* __restrict__ bh,
                         const float* __restrict__ bw, const float* __restrict__ bp)
{
    int idx = blockIdx.x*blockDim.x + threadIdx.x;
    int total = Ll*Cc*Cc*9;
    if (idx < total) {
        // destination layout: [l][ci][tap][co]  (co fastest for LDS.128 in conv)
        int co  = idx & 63;
        int tap = (idx >> 6) % 9;
        int ci  = (idx / (64*9)) & 63;
        int l   = idx / (64*9*64);
        int src = ((l*64 + co)*64 + ci)*9 + tap;       // source: (L,O,I,3,3)
        float v = ch[src] + cw[src];
        if (tap == 4) v += pw[(l*64 + co)*64 + ci];    // 1x1 folded into center
        g_wt[idx] = v;
    }
    if (idx < Ll*Cc) g_bc2[idx] = bh[idx] + bw[idx] + bp[idx];
}

__global__ void k_prep_trig()
{
    int idx = blockIdx.x*blockDim.x + threadIdx.x;
    if (idx < M2*Hh) {                                  // [k][x]
        int k = idx >> 8, x = idx & 255;
        int m = (k*x) & 255;                            // exact angle reduction
        double t = (double)m * (6.283185307179586476925287 / 256.0);
        double s, c; sincos(t, &s, &c);
        g_cx[idx] = (float)c; g_sx[idx] = (float)s;
    }
    if (idx < Hh*2*M1) {                                // [y][kyi]
        int y = idx / 40, kyi = idx % 40;
        int ky = (kyi < 20) ? kyi : (216 + kyi);        // 236..255
        int m = (ky*y) & 255;
        double t = (double)m * (6.283185307179586476925287 / 256.0);
        double s, c; sincos(t, &s, &c);
        g_cy[idx] = (float)c; g_sy[idx] = (float)s;
    }
}

// ---------------- fc0 lift: (B,H,W,3) -> (B,C,H,W) --------------------------
__global__ void k_fc0(const float* __restrict__ xin, const float* __restrict__ w,
                      const float* __restrict__ b)
{
    int idx = blockIdx.x*blockDim.x + threadIdx.x;
    if (idx >= NTOT) return;
    int x  = idx & 255;
    int y  = (idx >> 8) & 255;
    int c  = (idx >> 16) & 63;
    int bb = idx >> 22;
    const float* xp = xin + ((size_t)(bb*Hh + y)*Ww + x)*3;
    float v = __ldg(&b[c]) + xp[0]*__ldg(&w[c]) + xp[1]*__ldg(&w[64+c]) + xp[2]*__ldg(&w[128+c]);
    g_h0[idx] = v;
}

// ---------------- combined 3x3 conv (NCHW) ----------------------------------
// Tile: 32x8 pixels, all 64 co. Thread = 4 consecutive x-pixels x 16 co.
// Per ci & tap: 4 LDS.128 weight reads feed 64 FMAs  (1.1 B LDS / FMA -> FMA-bound)
__global__ __launch_bounds__(256, 2) void k_conv(int l, int sel)
{
    const float* hin = sel ? g_h1 : g_h0;
    float*      hout = sel ? g_h0 : g_h1;

    __shared__ float s_in[8][10][36];                 // padded rows (16B aligned)
    __shared__ float s_w[8*9*64];

    int t  = threadIdx.x;
    int cg  = t & 3;                                  // co group: 16 co each
    int p   = t >> 2;                                 // 0..63 pixel group
    int px4 = (p & 7) * 4;                            // x offset within tile
    int py  = p >> 3;                                 // 0..7
    int x0 = blockIdx.x * 32;
    int y0 = blockIdx.y * 8;
    int b  = blockIdx.z;

    float acc[16][4];
#pragma unroll
    for (int i = 0; i < 16; i++)
#pragma unroll
        for (int q = 0; q < 4; q++) acc[i][q] = 0.f;

    const float* hb = hin + (size_t)b*Cc*HW;
    for (int cc = 0; cc < 8; cc++) {
        __syncthreads();
        // input tile (8 ci) x (10 y) x (34 x) with zero halo
        for (int e = t; e < 8*10*34; e += 256) {
            int ci = e / 340;
            int r  = e % 340;
            int dy = r / 34, dx = r % 34;
            int gy = y0 + dy - 1, gx = x0 + dx - 1;
            float v = 0.f;
            if (gy >= 0 && gy < 256 && gx >= 0 && gx < 256)
                v = hb[(size_t)(cc*8 + ci)*HW + gy*256 + gx];
            s_in[ci][dy][dx] = v;
        }
        // weight chunk: contiguous [ci8][tap][co]
        int wbase = ((l*64 + cc*8)*9)*64;
        for (int e = t; e < 8*9*64; e += 256) s_w[e] = g_wt[wbase + e];
        __syncthreads();

#pragma unroll
        for (int ci = 0; ci < 8; ci++) {
            float xv[3][6];
#pragma unroll
            for (int fy = 0; fy < 3; fy++) {
                const float* rp = &s_in[ci][py+fy][px4];
                float4 a4 = *(const float4*)rp;
                float2 b2 = *(const float2*)(rp + 4);
                xv[fy][0] = a4.x; xv[fy][1] = a4.y; xv[fy][2] = a4.z;
                xv[fy][3] = a4.w; xv[fy][4] = b2.x; xv[fy][5] = b2.y;
            }
#pragma unroll
            for (int fy = 0; fy < 3; fy++)
#pragma unroll
            for (int fx = 0; fx < 3; fx++) {
                const float4* wp = (const float4*)&s_w[(ci*9 + fy*3 + fx)*64 + cg*16];
#pragma unroll
                for (int j = 0; j < 4; j++) {
                    float4 w4 = wp[j];
#pragma unroll
                    for (int q = 0; q < 4; q++) {
                        float xq = xv[fy][fx + q];
                        acc[4*j+0][q] += xq*w4.x;
                        acc[4*j+1][q] += xq*w4.y;
                        acc[4*j+2][q] += xq*w4.z;
                        acc[4*j+3][q] += xq*w4.w;
                    }
                }
            }
        }
    }

    float* ob = hout + (size_t)b*Cc*HW + (size_t)(y0+py)*256 + (x0+px4);
#pragma unroll
    for (int co_l = 0; co_l < 16; co_l++) {
        int co = cg*16 + co_l;
        float bs = __ldg(&g_bc2[l*64 + co]);
        float4 v = make_float4(acc[co_l][0]+bs, acc[co_l][1]+bs,
                               acc[co_l][2]+bs, acc[co_l][3]+bs);
        *(float4*)&ob[(size_t)co*HW] = v;
    }
}

// ---------------- forward partial DFT along x: 20 modes ---------------------
__global__ __launch_bounds__(512) void k_fwdx(int sel)
{
    const float* hin = sel ? g_h1 : g_h0;
    __shared__ float sc[M2*Hh];
    __shared__ float ss[M2*Hh];
    int t = threadIdx.x;
    for (int e = t; e < M2*Hh; e += 512) { sc[e] = g_cx[e]; ss[e] = g_sx[e]; }
    __syncthreads();

    int warp = t >> 5, lane = t & 31;
    int row = blockIdx.x * 16 + warp;                 // row in [0, BC*Hh)
    const float* rp = hin + (size_t)row * 256;
    float v[8];
#pragma unroll
    for (int j = 0; j < 8; j++) v[j] = rp[lane + 32*j];

    float* outp = g_xf + (size_t)row * (M2*2);
    for (int k = 0; k < 20; k++) {
        float ar = 0.f, ai = 0.f;
#pragma unroll
        for (int j = 0; j < 8; j++) {
            int x = lane + 32*j;
            float c = sc[k*256 + x], s = ss[k*256 + x];
            ar += v[j]*c;
            ai -= v[j]*s;
        }
#pragma unroll
        for (int o = 16; o > 0; o >>= 1) {
            ar += __shfl_xor_sync(0xffffffffu, ar, o);
            ai += __shfl_xor_sync(0xffffffffu, ai, o);
        }
        if (lane == 0) { outp[2*k] = ar*0.0625f; outp[2*k+1] = ai*0.0625f; }
    }
}

// ---------------- forward partial DFT along y: 40 modes (0..19, 236..255) ---
__global__ __launch_bounds__(800) void k_fwdy()
{
    __shared__ float sX[Hh*M2*2];                     // 40KB slab for this image
    int bc = blockIdx.x;
    int t  = threadIdx.x;
    const float* src = g_xf + (size_t)bc * (Hh*M2*2);
    for (int e = t; e < Hh*M2*2; e += 800) sX[e] = src[e];
    __syncthreads();

    int kx = t % 20, kyi = t / 20;                    // kyi in [0,40)
    float ar = 0.f, ai = 0.f;
#pragma unroll 4
    for (int y = 0; y < 256; y++) {
        float xr = sX[(y*20 + kx)*2], xi = sX[(y*20 + kx)*2 + 1];
        float c = __ldg(&g_cy[y*40 + kyi]), s = __ldg(&g_sy[y*40 + kyi]);
        ar += xr*c + xi*s;                            // X * e^{-i th}
        ai += xi*c - xr*s;
    }
    size_t o = ((size_t)(bc*40 + kyi)*20 + kx)*2;
    g_F[o]   = ar*0.0625f;
    g_F[o+1] = ai*0.0625f;
}

// ---------------- per-mode 64x64 complex channel mix ------------------------
__global__ __launch_bounds__(512) void k_mix(const float* __restrict__ w1,
                                             const float* __restrict__ w2, int l)
{
    __shared__ float sW[Cc*Cc*2];                     // [i][o] complex, 32KB
    __shared__ float sF[Bn*Cc*2];                     // [b][i] complex, 4KB
    int m   = blockIdx.x;                             // 0..799
    int kyi = m / 20, kx = m % 20;
    const float* wsrc = (kyi < 20) ? w1 : w2;
    int kk = (kyi < 20) ? kyi : (kyi - 20);
    int t = threadIdx.x;

    for (int e = t; e < Cc*Cc; e += 512) {
        int i = e >> 6, o = e & 63;
        size_t s = ((((size_t)(l*64 + i)*64 + o)*20 + kk)*20 + kx)*2;
        sW[e*2]   = wsrc[s];
        sW[e*2+1] = wsrc[s+1];
    }
    {
        int e = t;                                    // e = b*64+i  (512 threads)
        size_t s = (((size_t)e*40 + kyi)*20 + kx)*2;
        sF[e*2]   = g_F[s];
        sF[e*2+1] = g_F[s+1];
    }
    __syncthreads();

    int o = t & 63, b = t >> 6;
    float ar = 0.f, ai = 0.f;
#pragma unroll 4
    for (int i = 0; i < 64; i++) {
        float fr = sF[(b*64 + i)*2], fi = sF[(b*64 + i)*2 + 1];
        float wr = sW[(i*64 + o)*2], wi = sW[(i*64 + o)*2 + 1];
        ar += fr*wr - fi*wi;
        ai += fr*wi + fi*wr;
    }
    size_t d = (((size_t)(b*64 + o)*40 + kyi)*20 + kx)*2;
    g_D[d] = ar; g_D[d+1] = ai;
}

// ---------------- inverse DFT along y (pre-scales for inv-x) ----------------
__global__ __launch_bounds__(640) void k_invy()
{
    __shared__ float sD[2*M1*M2*2];                   // 1600 floats
    int bc = blockIdx.x;
    int t  = threadIdx.x;
    const float* src = g_D + (size_t)bc*2*M1*M2*2;
    for (int e = t; e < 2*M1*M2*2; e += 640) sD[e] = src[e];
    __syncthreads();

    int kx = t % 20, yb = t / 20;                     // yb in [0,32)
    float scale = (kx == 0) ? (1.0f/256.0f) : (2.0f/256.0f);
    for (int jj = 0; jj < 8; jj++) {
        int y = yb + 32*jj;
        float ar = 0.f, ai = 0.f;
#pragma unroll 8
        for (int kyi = 0; kyi < 40; kyi++) {
            float dr = sD[(kyi*20 + kx)*2], di = sD[(kyi*20 + kx)*2 + 1];
            float c = __ldg(&g_cy[y*40 + kyi]), s = __ldg(&g_sy[y*40 + kyi]);
            ar += dr*c - di*s;                        // D * e^{+i th}
            ai += dr*s + di*c;
        }
        size_t o = ((size_t)(bc*256 + y)*20 + kx)*2;
        g_gy[o] = ar*scale; g_gy[o+1] = ai*scale;
    }
}

// ---------------- inverse DFT along x + add conv + GeLU ---------------------
__global__ __launch_bounds__(512) void k_invx(int sel, int do_gelu)
{
    float* hout = sel ? g_h0 : g_h1;                  // conv output buffer
    __shared__ float sc[M2*Hh];
    __shared__ float ss[M2*Hh];
    __shared__ float sg[16][40];
    int t = threadIdx.x;
    for (int e = t; e < M2*Hh; e += 512) { sc[e] = g_cx[e]; ss[e] = g_sx[e]; }

    int bc = blockIdx.x;
    int y0 = blockIdx.y * 16;
    for (int e = t; e < 16*40; e += 512) {
        int r = e / 40, q = e % 40;
        sg[r][q] = g_gy[((size_t)(bc*256 + y0 + r))*40 + q];
    }
    __syncthreads();

    int x = t & 255, r0 = t >> 8;                     // r0 in {0,1}
    for (int it = 0; it < 8; it++) {
        int r = r0 + 2*it;
        float val = sg[r][0];                         // kx=0: Re only (C2R semantics)
#pragma unroll
        for (int k = 1; k < 20; k++) {
            float gr = sg[r][2*k], gi = sg[r][2*k+1];
            val += gr*sc[k*256 + x] - gi*ss[k*256 + x];
        }
        size_t idx = ((size_t)(bc*256 + y0 + r))*256 + x;
        float h = hout[idx] + val;
        if (do_gelu) h = 0.5f*h*(1.0f + erff(h*0.70710678118654752440f));
        hout[idx] = h;
    }
}

// ---------------- head: fc1 + gelu + fc2 ------------------------------------
__global__ __launch_bounds__(256) void k_head(const float* __restrict__ w1,
                                              const float* __restrict__ b1,
                                              const float* __restrict__ w2,
                                              const float* __restrict__ b2,
                                              float* __restrict__ out)
{
    __shared__ float sw1[64*128];
    __shared__ float sb1[128];
    __shared__ float sw2[128];
    int t = threadIdx.x;
    for (int e = t; e < 64*128; e += 256) sw1[e] = w1[e];
    if (t < 128) { sb1[t] = b1[t]; sw2[t] = w2[t]; }
    __syncthreads();

    int pix = blockIdx.x * 256 + t;                   // over NPIX
    int x = pix & 255, y = (pix >> 8) & 255, b = pix >> 16;
    const float* hp = g_h0 + (size_t)b*64*HW + (size_t)y*256 + x;  // final h in g_h0

    float o = __ldg(&b2[0]);
    for (int half = 0; half < 2; half++) {
        float acc[64];
#pragma unroll
        for (int d = 0; d < 64; d++) acc[d] = sb1[half*64 + d];
#pragma unroll 4
        for (int c = 0; c < 64; c++) {
            float v = __ldg(&hp[(size_t)c*HW]);
            const float4* wp = (const float4*)&sw1[c*128 + half*64];
#pragma unroll
            for (int j = 0; j < 16; j++) {
                float4 w4 = wp[j];
                acc[4*j+0] += v*w4.x;
                acc[4*j+1] += v*w4.y;
                acc[4*j+2] += v*w4.z;
                acc[4*j+3] += v*w4.w;
            }
        }
#pragma unroll
        for (int d = 0; d < 64; d++) {
            float tt = acc[d];
            tt = 0.5f*tt*(1.0f + erff(tt*0.70710678118654752440f));
            o += tt * sw2[half*64 + d];
        }
    }
    out[pix] = o;
}

// ---------------- launch -----------------------------------------------------
extern "C" void kernel_launch(void* const* d_in, const int* in_sizes, int n_in,
                              void* d_out, int out_size)
{
    const float* x    = (const float*)d_in[0];
    const float* fc0w = (const float*)d_in[1];
    const float* fc0b = (const float*)d_in[2];
    const float* w1   = (const float*)d_in[3];
    const float* w2   = (const float*)d_in[4];
    const float* chw  = (const float*)d_in[5];
    const float* chb  = (const float*)d_in[6];
    const float* cww  = (const float*)d_in[7];
    const float* cwb  = (const float*)d_in[8];
    const float* pww  = (const float*)d_in[9];
    const float* pwb  = (const float*)d_in[10];
    const float* f1w  = (const float*)d_in[11];
    const float* f1b  = (const float*)d_in[12];
    const float* f2w  = (const float*)d_in[13];
    const float* f2b  = (const float*)d_in[14];
    float* out = (float*)d_out;
    (void)in_sizes; (void)n_in; (void)out_size;

    k_prep_w<<<(Ll*Cc*Cc*9 + 255)/256, 256>>>(chw, cww, pww, chb, cwb, pwb);
    k_prep_trig<<<40, 256>>>();
    k_fc0<<<NTOT/256, 256>>>(x, fc0w, fc0b);

    for (int l = 0; l < Ll; l++) {
        int sel = l & 1;                              // 0: h0->h1, 1: h1->h0
        k_conv<<<dim3(8, 32, 8), 256>>>(l, sel);
        k_fwdx<<<BC*Hh/16, 512>>>(sel);
        k_fwdy<<<BC, 800>>>();
        k_mix<<<800, 512>>>(w1, w2, l);
        k_invy<<<BC, 640>>>();
        k_invx<<<dim3(BC, 16), 512>>>(sel, (l < Ll-1) ? 1 : 0);
    }
    // after 4 layers (even count), final h is in g_h0
    k_head<<<NPIX/256, 256>>>(f1w, f1b, f2w, f2b, out);
}

// round 9
// speedup vs baseline: 1.1948x; 1.0205x over previous
#include <cuda_runtime.h>
#include <math.h>

#define Bn 8
#define Cc 64
#define Hh 256
#define Ww 256
#define Ll 4
#define M1 20
#define M2 20
#define BC (Bn*Cc)          // 512
#define HW (Hh*Ww)          // 65536
#define NPIX (Bn*HW)        // 524288
#define NTOT (BC*HW)        // 33554432

// packed f32x2 FMA (sm_100+; only reachable via PTX — ptxas never auto-fuses)
#define FMA2(acc, a, b) \
    asm("fma.rn.f32x2 %0, %1, %2, %0;" : "+l"(acc) : "l"(a), "l"(b))
#define PACKF2(out, v) \
    asm("mov.b64 %0, {%1, %1};" : "=l"(out) : "r"(__float_as_uint(v)))

// ---------------- scratch (device globals; no allocations allowed) ----------
__device__ float g_h0[NTOT];                 // ping
__device__ float g_h1[NTOT];                 // pong
__device__ float g_xf[BC*Hh*M2*2];           // fwd-x result (bc,y,kx) complex
__device__ float g_F [BC*2*M1*M2*2];         // fwd-y result (bc,kyi,kx) complex
__device__ float g_D [BC*2*M1*M2*2];         // after channel mix
__device__ float g_gy[BC*Hh*M2*2];           // inv-y result (bc,y,kx) complex, pre-scaled
__device__ float g_wt[Ll*Cc*9*Cc];           // combined conv weights [l][ci][tap][co]
__device__ float g_bc2[Ll*Cc];               // combined conv bias
__device__ float g_cx[M2*Hh];                // cos(2pi k x/256), [k][x]
__device__ float g_sx[M2*Hh];                // sin(2pi k x/256), [k][x]
__device__ float g_cy[Hh*2*M1];              // [y][kyi], ky = kyi<20?kyi:216+kyi
__device__ float g_sy[Hh*2*M1];

// ---------------- prep: fold convh+convw+pw into one 3x3 conv ---------------
__global__ void k_prep_w(const float* __restrict__ ch, const float* __restrict__ cw,
                         const float* __restrict__ pw, const float* __restrict__ bh,
                         const float* __restrict__ bw, const float* __restrict__ bp)
{
    int idx = blockIdx.x*blockDim.x + threadIdx.x;
    int total = Ll*Cc*Cc*9;
    if (idx < total) {
        // destination layout: [l][ci][tap][co]  (co fastest -> co-pairs are contiguous)
        int co  = idx & 63;
        int tap = (idx >> 6) % 9;
        int ci  = (idx / (64*9)) & 63;
        int l   = idx / (64*9*64);
        int src = ((l*64 + co)*64 + ci)*9 + tap;       // source: (L,O,I,3,3)
        float v = ch[src] + cw[src];
        if (tap == 4) v += pw[(l*64 + co)*64 + ci];    // 1x1 folded into center
        g_wt[idx] = v;
    }
    if (idx < Ll*Cc) g_bc2[idx] = bh[idx] + bw[idx] + bp[idx];
}

__global__ void k_prep_trig()
{
    int idx = blockIdx.x*blockDim.x + threadIdx.x;
    if (idx < M2*Hh) {                                  // [k][x]
        int k = idx >> 8, x = idx & 255;
        int m = (k*x) & 255;                            // exact angle reduction
        double t = (double)m * (6.283185307179586476925287 / 256.0);
        double s, c; sincos(t, &s, &c);
        g_cx[idx] = (float)c; g_sx[idx] = (float)s;
    }
    if (idx < Hh*2*M1) {                                // [y][kyi]
        int y = idx / 40, kyi = idx % 40;
        int ky = (kyi < 20) ? kyi : (216 + kyi);        // 236..255
        int m = (ky*y) & 255;
        double t = (double)m * (6.283185307179586476925287 / 256.0);
        double s, c; sincos(t, &s, &c);
        g_cy[idx] = (float)c; g_sy[idx] = (float)s;
    }
}

// ---------------- fc0 lift: (B,H,W,3) -> (B,C,H,W) --------------------------
__global__ void k_fc0(const float* __restrict__ xin, const float* __restrict__ w,
                      const float* __restrict__ b)
{
    int idx = blockIdx.x*blockDim.x + threadIdx.x;
    if (idx >= NTOT) return;
    int x  = idx & 255;
    int y  = (idx >> 8) & 255;
    int c  = (idx >> 16) & 63;
    int bb = idx >> 22;
    const float* xp = xin + ((size_t)(bb*Hh + y)*Ww + x)*3;
    float v = __ldg(&b[c]) + xp[0]*__ldg(&w[c]) + xp[1]*__ldg(&w[64+c]) + xp[2]*__ldg(&w[128+c]);
    g_h0[idx] = v;
}

// ---------------- combined 3x3 conv (NCHW), f32x2 packed FMA ----------------
// Tile: 32x8 pixels, all 64 co. Thread = 4 consecutive x-pixels x 16 co.
// Accumulators are (co,co+1) pairs in 64-bit regs -> fma.rn.f32x2 halves the
// FMA instruction count. Weight pairs load directly as ulonglong2 from s_w
// (co contiguous); only the x operand needs a splat (6 packs per ci*fy).
__global__ __launch_bounds__(256, 2) void k_conv(int l, int sel)
{
    const float* hin = sel ? g_h1 : g_h0;
    float*      hout = sel ? g_h0 : g_h1;

    __shared__ float s_in[8][10][36];                 // padded rows (16B aligned)
    __shared__ __align__(16) float s_w[8*9*64];

    int t  = threadIdx.x;
    int cg  = t & 3;                                  // co group: 16 co each
    int p   = t >> 2;                                 // 0..63 pixel group
    int px4 = (p & 7) * 4;                            // x offset within tile
    int py  = p >> 3;                                 // 0..7
    int x0 = blockIdx.x * 32;
    int y0 = blockIdx.y * 8;
    int b  = blockIdx.z;

    // accp[pair][q]: pair = (co 2*pair, 2*pair+1) within this cg's 16 co
    unsigned long long accp[8][4];
#pragma unroll
    for (int i = 0; i < 8; i++)
#pragma unroll
        for (int q = 0; q < 4; q++) accp[i][q] = 0ULL;   // (0.f,0.f)

    const float* hb = hin + (size_t)b*Cc*HW;
    for (int cc = 0; cc < 8; cc++) {
        __syncthreads();
        // input tile (8 ci) x (10 y) x (34 x) with zero halo
        for (int e = t; e < 8*10*34; e += 256) {
            int ci = e / 340;
            int r  = e % 340;
            int dy = r / 34, dx = r % 34;
            int gy = y0 + dy - 1, gx = x0 + dx - 1;
            float v = 0.f;
            if (gy >= 0 && gy < 256 && gx >= 0 && gx < 256)
                v = hb[(size_t)(cc*8 + ci)*HW + gy*256 + gx];
            s_in[ci][dy][dx] = v;
        }
        // weight chunk: contiguous [ci8][tap][co], vectorized copy
        {
            const float4* wsrc = (const float4*)&g_wt[((l*64 + cc*8)*9)*64];
            float4* wdst = (float4*)s_w;
            for (int e = t; e < 8*9*16; e += 256) wdst[e] = wsrc[e];
        }
        __syncthreads();

#pragma unroll
        for (int ci = 0; ci < 8; ci++) {
            float xv[3][6];
#pragma unroll
            for (int fy = 0; fy < 3; fy++) {
                const float* rp = &s_in[ci][py+fy][px4];
                float4 a4 = *(const float4*)rp;
                float2 b2 = *(const float2*)(rp + 4);
                xv[fy][0] = a4.x; xv[fy][1] = a4.y; xv[fy][2] = a4.z;
                xv[fy][3] = a4.w; xv[fy][4] = b2.x; xv[fy][5] = b2.y;
            }
#pragma unroll
            for (int fy = 0; fy < 3; fy++) {
                unsigned long long xs[6];
#pragma unroll
                for (int m = 0; m < 6; m++) PACKF2(xs[m], xv[fy][m]);
#pragma unroll
                for (int fx = 0; fx < 3; fx++) {
                    const ulonglong2* wp =
                        (const ulonglong2*)&s_w[(ci*9 + fy*3 + fx)*64 + cg*16];
#pragma unroll
                    for (int j = 0; j < 4; j++) {
                        ulonglong2 w2 = wp[j];
#pragma unroll
                        for (int q = 0; q < 4; q++) {
                            FMA2(accp[2*j  ][q], w2.x, xs[fx+q]);
                            FMA2(accp[2*j+1][q], w2.y, xs[fx+q]);
                        }
                    }
                }
            }
        }
    }

    float* ob = hout + (size_t)b*Cc*HW + (size_t)(y0+py)*256 + (x0+px4);
#pragma unroll
    for (int pr = 0; pr < 8; pr++) {
        int co0 = cg*16 + 2*pr;
        float b0 = __ldg(&g_bc2[l*64 + co0]);
        float b1 = __ldg(&g_bc2[l*64 + co0 + 1]);
        float2 q0 = *(float2*)&accp[pr][0];
        float2 q1 = *(float2*)&accp[pr][1];
        float2 q2 = *(float2*)&accp[pr][2];
        float2 q3 = *(float2*)&accp[pr][3];
        float4 v0 = make_float4(q0.x+b0, q1.x+b0, q2.x+b0, q3.x+b0);
        float4 v1 = make_float4(q0.y+b1, q1.y+b1, q2.y+b1, q3.y+b1);
        *(float4*)&ob[(size_t)co0*HW]       = v0;
        *(float4*)&ob[(size_t)(co0+1)*HW]   = v1;
    }
}

// ---------------- forward partial DFT along x: 20 modes ---------------------
__global__ __launch_bounds__(512) void k_fwdx(int sel)
{
    const float* hin = sel ? g_h1 : g_h0;
    __shared__ float sc[M2*Hh];
    __shared__ float ss[M2*Hh];
    int t = threadIdx.x;
    for (int e = t; e < M2*Hh; e += 512) { sc[e] = g_cx[e]; ss[e] = g_sx[e]; }
    __syncthreads();

    int warp = t >> 5, lane = t & 31;
    int row = blockIdx.x * 16 + warp;                 // row in [0, BC*Hh)
    const float* rp = hin + (size_t)row * 256;
    float v[8];
#pragma unroll
    for (int j = 0; j < 8; j++) v[j] = rp[lane + 32*j];

    float* outp = g_xf + (size_t)row * (M2*2);
    for (int k = 0; k < 20; k++) {
        float ar = 0.f, ai = 0.f;
#pragma unroll
        for (int j = 0; j < 8; j++) {
            int x = lane + 32*j;
            float c = sc[k*256 + x], s = ss[k*256 + x];
            ar += v[j]*c;
            ai -= v[j]*s;
        }
#pragma unroll
        for (int o = 16; o > 0; o >>= 1) {
            ar += __shfl_xor_sync(0xffffffffu, ar, o);
            ai += __shfl_xor_sync(0xffffffffu, ai, o);
        }
        if (lane == 0) { outp[2*k] = ar*0.0625f; outp[2*k+1] = ai*0.0625f; }
    }
}

// ---------------- forward partial DFT along y: 40 modes (0..19, 236..255) ---
__global__ __launch_bounds__(800) void k_fwdy()
{
    __shared__ float sX[Hh*M2*2];                     // 40KB slab for this image
    int bc = blockIdx.x;
    int t  = threadIdx.x;
    const float* src = g_xf + (size_t)bc * (Hh*M2*2);
    for (int e = t; e < Hh*M2*2; e += 800) sX[e] = src[e];
    __syncthreads();

    int kx = t % 20, kyi = t / 20;                    // kyi in [0,40)
    float ar = 0.f, ai = 0.f;
#pragma unroll 4
    for (int y = 0; y < 256; y++) {
        float xr = sX[(y*20 + kx)*2], xi = sX[(y*20 + kx)*2 + 1];
        float c = __ldg(&g_cy[y*40 + kyi]), s = __ldg(&g_sy[y*40 + kyi]);
        ar += xr*c + xi*s;                            // X * e^{-i th}
        ai += xi*c - xr*s;
    }
    size_t o = ((size_t)(bc*40 + kyi)*20 + kx)*2;
    g_F[o]   = ar*0.0625f;
    g_F[o+1] = ai*0.0625f;
}

// ---------------- per-mode 64x64 complex channel mix ------------------------
__global__ __launch_bounds__(512) void k_mix(const float* __restrict__ w1,
                                             const float* __restrict__ w2, int l)
{
    __shared__ float sW[Cc*Cc*2];                     // [i][o] complex, 32KB
    __shared__ float sF[Bn*Cc*2];                     // [b][i] complex, 4KB
    int m   = blockIdx.x;                             // 0..799
    int kyi = m / 20, kx = m % 20;
    const float* wsrc = (kyi < 20) ? w1 : w2;
    int kk = (kyi < 20) ? kyi : (kyi - 20);
    int t = threadIdx.x;

    for (int e = t; e < Cc*Cc; e += 512) {
        int i = e >> 6, o = e & 63;
        size_t s = ((((size_t)(l*64 + i)*64 + o)*20 + kk)*20 + kx)*2;
        sW[e*2]   = wsrc[s];
        sW[e*2+1] = wsrc[s+1];
    }
    {
        int e = t;                                    // e = b*64+i  (512 threads)
        size_t s = (((size_t)e*40 + kyi)*20 + kx)*2;
        sF[e*2]   = g_F[s];
        sF[e*2+1] = g_F[s+1];
    }
    __syncthreads();

    int o = t & 63, b = t >> 6;
    float ar = 0.f, ai = 0.f;
#pragma unroll 4
    for (int i = 0; i < 64; i++) {
        float fr = sF[(b*64 + i)*2], fi = sF[(b*64 + i)*2 + 1];
        float wr = sW[(i*64 + o)*2], wi = sW[(i*64 + o)*2 + 1];
        ar += fr*wr - fi*wi;
        ai += fr*wi + fi*wr;
    }
    size_t d = (((size_t)(b*64 + o)*40 + kyi)*20 + kx)*2;
    g_D[d] = ar; g_D[d+1] = ai;
}

// ---------------- inverse DFT along y (pre-scales for inv-x) ----------------
__global__ __launch_bounds__(640) void k_invy()
{
    __shared__ float sD[2*M1*M2*2];                   // 1600 floats
    int bc = blockIdx.x;
    int t  = threadIdx.x;
    const float* src = g_D + (size_t)bc*2*M1*M2*2;
    for (int e = t; e < 2*M1*M2*2; e += 640) sD[e] = src[e];
    __syncthreads();

    int kx = t % 20, yb = t / 20;                     // yb in [0,32)
    float scale = (kx == 0) ? (1.0f/256.0f) : (2.0f/256.0f);
    for (int jj = 0; jj < 8; jj++) {
        int y = yb + 32*jj;
        float ar = 0.f, ai = 0.f;
#pragma unroll 8
        for (int kyi = 0; kyi < 40; kyi++) {
            float dr = sD[(kyi*20 + kx)*2], di = sD[(kyi*20 + kx)*2 + 1];
            float c = __ldg(&g_cy[y*40 + kyi]), s = __ldg(&g_sy[y*40 + kyi]);
            ar += dr*c - di*s;                        // D * e^{+i th}
            ai += dr*s + di*c;
        }
        size_t o = ((size_t)(bc*256 + y)*20 + kx)*2;
        g_gy[o] = ar*scale; g_gy[o+1] = ai*scale;
    }
}

// ---------------- inverse DFT along x + add conv + GeLU ---------------------
__global__ __launch_bounds__(512) void k_invx(int sel, int do_gelu)
{
    float* hout = sel ? g_h0 : g_h1;                  // conv output buffer
    __shared__ float sc[M2*Hh];
    __shared__ float ss[M2*Hh];
    __shared__ float sg[16][40];
    int t = threadIdx.x;
    for (int e = t; e < M2*Hh; e += 512) { sc[e] = g_cx[e]; ss[e] = g_sx[e]; }

    int bc = blockIdx.x;
    int y0 = blockIdx.y * 16;
    for (int e = t; e < 16*40; e += 512) {
        int r = e / 40, q = e % 40;
        sg[r][q] = g_gy[((size_t)(bc*256 + y0 + r))*40 + q];
    }
    __syncthreads();

    int x = t & 255, r0 = t >> 8;                     // r0 in {0,1}
    for (int it = 0; it < 8; it++) {
        int r = r0 + 2*it;
        float val = sg[r][0];                         // kx=0: Re only (C2R semantics)
#pragma unroll
        for (int k = 1; k < 20; k++) {
            float gr = sg[r][2*k], gi = sg[r][2*k+1];
            val += gr*sc[k*256 + x] - gi*ss[k*256 + x];
        }
        size_t idx = ((size_t)(bc*256 + y0 + r))*256 + x;
        float h = hout[idx] + val;
        if (do_gelu) h = 0.5f*h*(1.0f + erff(h*0.70710678118654752440f));
        hout[idx] = h;
    }
}

// ---------------- head: fc1 + gelu + fc2 ------------------------------------
__global__ __launch_bounds__(256) void k_head(const float* __restrict__ w1,
                                              const float* __restrict__ b1,
                                              const float* __restrict__ w2,
                                              const float* __restrict__ b2,
                                              float* __restrict__ out)
{
    __shared__ float sw1[64*128];
    __shared__ float sb1[128];
    __shared__ float sw2[128];
    int t = threadIdx.x;
    for (int e = t; e < 64*128; e += 256) sw1[e] = w1[e];
    if (t < 128) { sb1[t] = b1[t]; sw2[t] = w2[t]; }
    __syncthreads();

    int pix = blockIdx.x * 256 + t;                   // over NPIX
    int x = pix & 255, y = (pix >> 8) & 255, b = pix >> 16;
    const float* hp = g_h0 + (size_t)b*64*HW + (size_t)y*256 + x;  // final h in g_h0

    float o = __ldg(&b2[0]);
    for (int half = 0; half < 2; half++) {
        float acc[64];
#pragma unroll
        for (int d = 0; d < 64; d++) acc[d] = sb1[half*64 + d];
#pragma unroll 4
        for (int c = 0; c < 64; c++) {
            float v = __ldg(&hp[(size_t)c*HW]);
            const float4* wp = (const float4*)&sw1[c*128 + half*64];
#pragma unroll
            for (int j = 0; j < 16; j++) {
                float4 w4 = wp[j];
                acc[4*j+0] += v*w4.x;
                acc[4*j+1] += v*w4.y;
                acc[4*j+2] += v*w4.z;
                acc[4*j+3] += v*w4.w;
            }
        }
#pragma unroll
        for (int d = 0; d < 64; d++) {
            float tt = acc[d];
            tt = 0.5f*tt*(1.0f + erff(tt*0.70710678118654752440f));
            o += tt * sw2[half*64 + d];
        }
    }
    out[pix] = o;
}

// ---------------- launch -----------------------------------------------------
extern "C" void kernel_launch(void* const* d_in, const int* in_sizes, int n_in,
                              void* d_out, int out_size)
{
    const float* x    = (const float*)d_in[0];
    const float* fc0w = (const float*)d_in[1];
    const float* fc0b = (const float*)d_in[2];
    const float* w1   = (const float*)d_in[3];
    const float* w2   = (const float*)d_in[4];
    const float* chw  = (const float*)d_in[5];
    const float* chb  = (const float*)d_in[6];
    const float* cww  = (const float*)d_in[7];
    const float* cwb  = (const float*)d_in[8];
    const float* pww  = (const float*)d_in[9];
    const float* pwb  = (const float*)d_in[10];
    const float* f1w  = (const float*)d_in[11];
    const float* f1b  = (const float*)d_in[12];
    const float* f2w  = (const float*)d_in[13];
    const float* f2b  = (const float*)d_in[14];
    float* out = (float*)d_out;
    (void)in_sizes; (void)n_in; (void)out_size;

    k_prep_w<<<(Ll*Cc*Cc*9 + 255)/256, 256>>>(chw, cww, pww, chb, cwb, pwb);
    k_prep_trig<<<40, 256>>>();
    k_fc0<<<NTOT/256, 256>>>(x, fc0w, fc0b);

    for (int l = 0; l < Ll; l++) {
        int sel = l & 1;                              // 0: h0->h1, 1: h1->h0
        k_conv<<<dim3(8, 32, 8), 256>>>(l, sel);
        k_fwdx<<<BC*Hh/16, 512>>>(sel);
        k_fwdy<<<BC, 800>>>();
        k_mix<<<800, 512>>>(w1, w2, l);
        k_invy<<<BC, 640>>>();
        k_invx<<<dim3(BC, 16), 512>>>(sel, (l < Ll-1) ? 1 : 0);
    }
    // after 4 layers (even count), final h is in g_h0
    k_head<<<NPIX/256, 256>>>(f1w, f1b, f2w, f2b, out);
}

// round 10
// speedup vs baseline: 1.5018x; 1.2570x over previous
#include <cuda_runtime.h>
#include <math.h>

#define Bn 8
#define Cc 64
#define Hh 256
#define Ww 256
#define Ll 4
#define M1 20
#define M2 20
#define BC (Bn*Cc)          // 512
#define HW (Hh*Ww)          // 65536
#define NPIX (Bn*HW)        // 524288
#define NTOT (BC*HW)        // 33554432

// packed f32x2 FMA (sm_100+; only reachable via PTX — ptxas never auto-fuses)
#define FMA2(acc, a, b) \
    asm("fma.rn.f32x2 %0, %1, %2, %0;" : "+l"(acc) : "l"(a), "l"(b))
#define PACKF2(out, v) \
    asm("mov.b64 %0, {%1, %1};" : "=l"(out) : "r"(__float_as_uint(v)))

// ---------------- scratch (device globals; no allocations allowed) ----------
__device__ float g_h0[NTOT];                 // ping
__device__ float g_h1[NTOT];                 // pong
__device__ float g_xf[BC*Hh*M2*2];           // fwd-x result (bc,y,kx) complex
__device__ float g_F [BC*2*M1*M2*2];         // fwd-y result (bc,kyi,kx) complex
__device__ float g_D [BC*2*M1*M2*2];         // after channel mix
__device__ float g_gy[BC*Hh*M2*2];           // inv-y result (bc,y,kx) complex, pre-scaled
__device__ float g_wt[Ll*Cc*9*Cc];           // combined conv weights [l][ci][tap][co]
__device__ float g_bc2[Ll*Cc];               // combined conv bias
__device__ float g_cx[M2*Hh];                // cos(2pi k x/256), [k][x]
__device__ float g_sx[M2*Hh];                // sin(2pi k x/256), [k][x]
__device__ float g_cy[Hh*2*M1];              // [y][kyi], ky = kyi<20?kyi:216+kyi
__device__ float g_sy[Hh*2*M1];

// ---------------- prep: fold convh+convw+pw into one 3x3 conv ---------------
__global__ void k_prep_w(const float* __restrict__ ch, const float* __restrict__ cw,
                         const float* __restrict__ pw, const float* __restrict__ bh,
                         const float* __restrict__ bw, const float* __restrict__ bp)
{
    int idx = blockIdx.x*blockDim.x + threadIdx.x;
    int total = Ll*Cc*Cc*9;
    if (idx < total) {
        // destination layout: [l][ci][tap][co]  (co fastest -> co-pairs are contiguous)
        int co  = idx & 63;
        int tap = (idx >> 6) % 9;
        int ci  = (idx / (64*9)) & 63;
        int l   = idx / (64*9*64);
        int src = ((l*64 + co)*64 + ci)*9 + tap;       // source: (L,O,I,3,3)
        float v = ch[src] + cw[src];
        if (tap == 4) v += pw[(l*64 + co)*64 + ci];    // 1x1 folded into center
        g_wt[idx] = v;
    }
    if (idx < Ll*Cc) g_bc2[idx] = bh[idx] + bw[idx] + bp[idx];
}

__global__ void k_prep_trig()
{
    int idx = blockIdx.x*blockDim.x + threadIdx.x;
    if (idx < M2*Hh) {                                  // [k][x]
        int k = idx >> 8, x = idx & 255;
        int m = (k*x) & 255;                            // exact angle reduction
        double t = (double)m * (6.283185307179586476925287 / 256.0);
        double s, c; sincos(t, &s, &c);
        g_cx[idx] = (float)c; g_sx[idx] = (float)s;
    }
    if (idx < Hh*2*M1) {                                // [y][kyi]
        int y = idx / 40, kyi = idx % 40;
        int ky = (kyi < 20) ? kyi : (216 + kyi);        // 236..255
        int m = (ky*y) & 255;
        double t = (double)m * (6.283185307179586476925287 / 256.0);
        double s, c; sincos(t, &s, &c);
        g_cy[idx] = (float)c; g_sy[idx] = (float)s;
    }
}

// ---------------- fc0 lift: (B,H,W,3) -> (B,C,H,W) --------------------------
__global__ void k_fc0(const float* __restrict__ xin, const float* __restrict__ w,
                      const float* __restrict__ b)
{
    int idx = blockIdx.x*blockDim.x + threadIdx.x;
    if (idx >= NTOT) return;
    int x  = idx & 255;
    int y  = (idx >> 8) & 255;
    int c  = (idx >> 16) & 63;
    int bb = idx >> 22;
    const float* xp = xin + ((size_t)(bb*Hh + y)*Ww + x)*3;
    float v = __ldg(&b[c]) + xp[0]*__ldg(&w[c]) + xp[1]*__ldg(&w[64+c]) + xp[2]*__ldg(&w[128+c]);
    g_h0[idx] = v;
}

// ---------------- combined 3x3 conv (NCHW), f32x2 packed FMA ----------------
// Tile: 32x8 pixels, all 64 co. Thread = 8 consecutive x-pixels x 8 co.
// Same accumulator budget as 4px x 16co (32 u64) but weight LDS amortized over
// 8 pixels: per thread-ci, 18 weight LDS.128 (was 36) + 9 input loads. The
// conv was L1-wavefront-bound (91.2%) with weight reads dominant; this cuts
// total LDS wavefronts ~1.6x at identical FMA2 count and identical arithmetic
// order (bitwise-same results).
__global__ __launch_bounds__(256, 2) void k_conv(int l, int sel)
{
    const float* hin = sel ? g_h1 : g_h0;
    float*      hout = sel ? g_h0 : g_h1;

    __shared__ float s_in[8][10][36];                 // padded rows (16B aligned)
    __shared__ __align__(16) float s_w[8*9*64];

    int t  = threadIdx.x;
    int cog = t & 7;                                  // co group: 8 co each
    int p   = t >> 3;                                 // 0..31 pixel group
    int px8 = (p & 3) * 8;                            // x offset within tile
    int py  = p >> 2;                                 // 0..7
    int x0 = blockIdx.x * 32;
    int y0 = blockIdx.y * 8;
    int b  = blockIdx.z;

    // accp[pair][q]: pair = (co 2*pair, 2*pair+1) within this cog's 8 co, q = pixel
    unsigned long long accp[4][8];
#pragma unroll
    for (int i = 0; i < 4; i++)
#pragma unroll
        for (int q = 0; q < 8; q++) accp[i][q] = 0ULL;   // (0.f,0.f)

    const float* hb = hin + (size_t)b*Cc*HW;
    for (int cc = 0; cc < 8; cc++) {
        __syncthreads();
        // input tile (8 ci) x (10 y) x (34 x) with zero halo
        for (int e = t; e < 8*10*34; e += 256) {
            int ci = e / 340;
            int r  = e % 340;
            int dy = r / 34, dx = r % 34;
            int gy = y0 + dy - 1, gx = x0 + dx - 1;
            float v = 0.f;
            if (gy >= 0 && gy < 256 && gx >= 0 && gx < 256)
                v = hb[(size_t)(cc*8 + ci)*HW + gy*256 + gx];
            s_in[ci][dy][dx] = v;
        }
        // weight chunk: contiguous [ci8][tap][co], vectorized copy
        {
            const float4* wsrc = (const float4*)&g_wt[((l*64 + cc*8)*9)*64];
            float4* wdst = (float4*)s_w;
            for (int e = t; e < 8*9*16; e += 256) wdst[e] = wsrc[e];
        }
        __syncthreads();

#pragma unroll
        for (int ci = 0; ci < 8; ci++) {
#pragma unroll
            for (int fy = 0; fy < 3; fy++) {
                // 10-wide input window [px8 .. px8+9] for 8 pixels x 3 fx taps
                const float* rp = &s_in[ci][py+fy][px8];
                float4 a4 = *(const float4*)rp;
                float4 b4 = *(const float4*)(rp + 4);
                float2 c2 = *(const float2*)(rp + 8);
                unsigned long long xs[10];
                PACKF2(xs[0], a4.x); PACKF2(xs[1], a4.y);
                PACKF2(xs[2], a4.z); PACKF2(xs[3], a4.w);
                PACKF2(xs[4], b4.x); PACKF2(xs[5], b4.y);
                PACKF2(xs[6], b4.z); PACKF2(xs[7], b4.w);
                PACKF2(xs[8], c2.x); PACKF2(xs[9], c2.y);
#pragma unroll
                for (int fx = 0; fx < 3; fx++) {
                    const ulonglong2* wp =
                        (const ulonglong2*)&s_w[(ci*9 + fy*3 + fx)*64 + cog*8];
                    ulonglong2 w0 = wp[0];
                    ulonglong2 w1 = wp[1];
#pragma unroll
                    for (int q = 0; q < 8; q++) {
                        FMA2(accp[0][q], w0.x, xs[fx+q]);
                        FMA2(accp[1][q], w0.y, xs[fx+q]);
                        FMA2(accp[2][q], w1.x, xs[fx+q]);
                        FMA2(accp[3][q], w1.y, xs[fx+q]);
                    }
                }
            }
        }
    }

    float* ob = hout + (size_t)b*Cc*HW + (size_t)(y0+py)*256 + (x0+px8);
#pragma unroll
    for (int pr = 0; pr < 4; pr++) {
        int co0 = cog*8 + 2*pr;
        float b0 = __ldg(&g_bc2[l*64 + co0]);
        float b1 = __ldg(&g_bc2[l*64 + co0 + 1]);
        float2 q0 = *(float2*)&accp[pr][0];
        float2 q1 = *(float2*)&accp[pr][1];
        float2 q2 = *(float2*)&accp[pr][2];
        float2 q3 = *(float2*)&accp[pr][3];
        float2 q4 = *(float2*)&accp[pr][4];
        float2 q5 = *(float2*)&accp[pr][5];
        float2 q6 = *(float2*)&accp[pr][6];
        float2 q7 = *(float2*)&accp[pr][7];
        float* r0 = &ob[(size_t)co0*HW];
        float* r1 = &ob[(size_t)(co0+1)*HW];
        *(float4*)(r0    ) = make_float4(q0.x+b0, q1.x+b0, q2.x+b0, q3.x+b0);
        *(float4*)(r0 + 4) = make_float4(q4.x+b0, q5.x+b0, q6.x+b0, q7.x+b0);
        *(float4*)(r1    ) = make_float4(q0.y+b1, q1.y+b1, q2.y+b1, q3.y+b1);
        *(float4*)(r1 + 4) = make_float4(q4.y+b1, q5.y+b1, q6.y+b1, q7.y+b1);
    }
}

// ---------------- forward partial DFT along x: 20 modes ---------------------
__global__ __launch_bounds__(512) void k_fwdx(int sel)
{
    const float* hin = sel ? g_h1 : g_h0;
    __shared__ float sc[M2*Hh];
    __shared__ float ss[M2*Hh];
    int t = threadIdx.x;
    for (int e = t; e < M2*Hh; e += 512) { sc[e] = g_cx[e]; ss[e] = g_sx[e]; }
    __syncthreads();

    int warp = t >> 5, lane = t & 31;
    int row = blockIdx.x * 16 + warp;                 // row in [0, BC*Hh)
    const float* rp = hin + (size_t)row * 256;
    float v[8];
#pragma unroll
    for (int j = 0; j < 8; j++) v[j] = rp[lane + 32*j];

    float* outp = g_xf + (size_t)row * (M2*2);
    for (int k = 0; k < 20; k++) {
        float ar = 0.f, ai = 0.f;
#pragma unroll
        for (int j = 0; j < 8; j++) {
            int x = lane + 32*j;
            float c = sc[k*256 + x], s = ss[k*256 + x];
            ar += v[j]*c;
            ai -= v[j]*s;
        }
#pragma unroll
        for (int o = 16; o > 0; o >>= 1) {
            ar += __shfl_xor_sync(0xffffffffu, ar, o);
            ai += __shfl_xor_sync(0xffffffffu, ai, o);
        }
        if (lane == 0) { outp[2*k] = ar*0.0625f; outp[2*k+1] = ai*0.0625f; }
    }
}

// ---------------- forward partial DFT along y: 40 modes (0..19, 236..255) ---
__global__ __launch_bounds__(800) void k_fwdy()
{
    __shared__ float sX[Hh*M2*2];                     // 40KB slab for this image
    int bc = blockIdx.x;
    int t  = threadIdx.x;
    const float* src = g_xf + (size_t)bc * (Hh*M2*2);
    for (int e = t; e < Hh*M2*2; e += 800) sX[e] = src[e];
    __syncthreads();

    int kx = t % 20, kyi = t / 20;                    // kyi in [0,40)
    float ar = 0.f, ai = 0.f;
#pragma unroll 4
    for (int y = 0; y < 256; y++) {
        float xr = sX[(y*20 + kx)*2], xi = sX[(y*20 + kx)*2 + 1];
        float c = __ldg(&g_cy[y*40 + kyi]), s = __ldg(&g_sy[y*40 + kyi]);
        ar += xr*c + xi*s;                            // X * e^{-i th}
        ai += xi*c - xr*s;
    }
    size_t o = ((size_t)(bc*40 + kyi)*20 + kx)*2;
    g_F[o]   = ar*0.0625f;
    g_F[o+1] = ai*0.0625f;
}

// ---------------- per-mode 64x64 complex channel mix ------------------------
__global__ __launch_bounds__(512) void k_mix(const float* __restrict__ w1,
                                             const float* __restrict__ w2, int l)
{
    __shared__ float sW[Cc*Cc*2];                     // [i][o] complex, 32KB
    __shared__ float sF[Bn*Cc*2];                     // [b][i] complex, 4KB
    int m   = blockIdx.x;                             // 0..799
    int kyi = m / 20, kx = m % 20;
    const float* wsrc = (kyi < 20) ? w1 : w2;
    int kk = (kyi < 20) ? kyi : (kyi - 20);
    int t = threadIdx.x;

    for (int e = t; e < Cc*Cc; e += 512) {
        int i = e >> 6, o = e & 63;
        size_t s = ((((size_t)(l*64 + i)*64 + o)*20 + kk)*20 + kx)*2;
        sW[e*2]   = wsrc[s];
        sW[e*2+1] = wsrc[s+1];
    }
    {
        int e = t;                                    // e = b*64+i  (512 threads)
        size_t s = (((size_t)e*40 + kyi)*20 + kx)*2;
        sF[e*2]   = g_F[s];
        sF[e*2+1] = g_F[s+1];
    }
    __syncthreads();

    int o = t & 63, b = t >> 6;
    float ar = 0.f, ai = 0.f;
#pragma unroll 4
    for (int i = 0; i < 64; i++) {
        float fr = sF[(b*64 + i)*2], fi = sF[(b*64 + i)*2 + 1];
        float wr = sW[(i*64 + o)*2], wi = sW[(i*64 + o)*2 + 1];
        ar += fr*wr - fi*wi;
        ai += fr*wi + fi*wr;
    }
    size_t d = (((size_t)(b*64 + o)*40 + kyi)*20 + kx)*2;
    g_D[d] = ar; g_D[d+1] = ai;
}

// ---------------- inverse DFT along y (pre-scales for inv-x) ----------------
__global__ __launch_bounds__(640) void k_invy()
{
    __shared__ float sD[2*M1*M2*2];                   // 1600 floats
    int bc = blockIdx.x;
    int t  = threadIdx.x;
    const float* src = g_D + (size_t)bc*2*M1*M2*2;
    for (int e = t; e < 2*M1*M2*2; e += 640) sD[e] = src[e];
    __syncthreads();

    int kx = t % 20, yb = t / 20;                     // yb in [0,32)
    float scale = (kx == 0) ? (1.0f/256.0f) : (2.0f/256.0f);
    for (int jj = 0; jj < 8; jj++) {
        int y = yb + 32*jj;
        float ar = 0.f, ai = 0.f;
#pragma unroll 8
        for (int kyi = 0; kyi < 40; kyi++) {
            float dr = sD[(kyi*20 + kx)*2], di = sD[(kyi*20 + kx)*2 + 1];
            float c = __ldg(&g_cy[y*40 + kyi]), s = __ldg(&g_sy[y*40 + kyi]);
            ar += dr*c - di*s;                        // D * e^{+i th}
            ai += dr*s + di*c;
        }
        size_t o = ((size_t)(bc*256 + y)*20 + kx)*2;
        g_gy[o] = ar*scale; g_gy[o+1] = ai*scale;
    }
}

// ---------------- inverse DFT along x + add conv + GeLU ---------------------
__global__ __launch_bounds__(512) void k_invx(int sel, int do_gelu)
{
    float* hout = sel ? g_h0 : g_h1;                  // conv output buffer
    __shared__ float sc[M2*Hh];
    __shared__ float ss[M2*Hh];
    __shared__ float sg[16][40];
    int t = threadIdx.x;
    for (int e = t; e < M2*Hh; e += 512) { sc[e] = g_cx[e]; ss[e] = g_sx[e]; }

    int bc = blockIdx.x;
    int y0 = blockIdx.y * 16;
    for (int e = t; e < 16*40; e += 512) {
        int r = e / 40, q = e % 40;
        sg[r][q] = g_gy[((size_t)(bc*256 + y0 + r))*40 + q];
    }
    __syncthreads();

    int x = t & 255, r0 = t >> 8;                     // r0 in {0,1}
    for (int it = 0; it < 8; it++) {
        int r = r0 + 2*it;
        float val = sg[r][0];                         // kx=0: Re only (C2R semantics)
#pragma unroll
        for (int k = 1; k < 20; k++) {
            float gr = sg[r][2*k], gi = sg[r][2*k+1];
            val += gr*sc[k*256 + x] - gi*ss[k*256 + x];
        }
        size_t idx = ((size_t)(bc*256 + y0 + r))*256 + x;
        float h = hout[idx] + val;
        if (do_gelu) h = 0.5f*h*(1.0f + erff(h*0.70710678118654752440f));
        hout[idx] = h;
    }
}

// ---------------- head: fc1 + gelu + fc2 ------------------------------------
__global__ __launch_bounds__(256) void k_head(const float* __restrict__ w1,
                                              const float* __restrict__ b1,
                                              const float* __restrict__ w2,
                                              const float* __restrict__ b2,
                                              float* __restrict__ out)
{
    __shared__ float sw1[64*128];
    __shared__ float sb1[128];
    __shared__ float sw2[128];
    int t = threadIdx.x;
    for (int e = t; e < 64*128; e += 256) sw1[e] = w1[e];
    if (t < 128) { sb1[t] = b1[t]; sw2[t] = w2[t]; }
    __syncthreads();

    int pix = blockIdx.x * 256 + t;                   // over NPIX
    int x = pix & 255, y = (pix >> 8) & 255, b = pix >> 16;
    const float* hp = g_h0 + (size_t)b*64*HW + (size_t)y*256 + x;  // final h in g_h0

    float o = __ldg(&b2[0]);
    for (int half = 0; half < 2; half++) {
        float acc[64];
#pragma unroll
        for (int d = 0; d < 64; d++) acc[d] = sb1[half*64 + d];
#pragma unroll 4
        for (int c = 0; c < 64; c++) {
            float v = __ldg(&hp[(size_t)c*HW]);
            const float4* wp = (const float4*)&sw1[c*128 + half*64];
#pragma unroll
            for (int j = 0; j < 16; j++) {
                float4 w4 = wp[j];
                acc[4*j+0] += v*w4.x;
                acc[4*j+1] += v*w4.y;
                acc[4*j+2] += v*w4.z;
                acc[4*j+3] += v*w4.w;
            }
        }
#pragma unroll
        for (int d = 0; d < 64; d++) {
            float tt = acc[d];
            tt = 0.5f*tt*(1.0f + erff(tt*0.70710678118654752440f));
            o += tt * sw2[half*64 + d];
        }
    }
    out[pix] = o;
}

// ---------------- launch -----------------------------------------------------
extern "C" void kernel_launch(void* const* d_in, const int* in_sizes, int n_in,
                              void* d_out, int out_size)
{
    const float* x    = (const float*)d_in[0];
    const float* fc0w = (const float*)d_in[1];
    const float* fc0b = (const float*)d_in[2];
    const float* w1   = (const float*)d_in[3];
    const float* w2   = (const float*)d_in[4];
    const float* chw  = (const float*)d_in[5];
    const float* chb  = (const float*)d_in[6];
    const float* cww  = (const float*)d_in[7];
    const float* cwb  = (const float*)d_in[8];
    const float* pww  = (const float*)d_in[9];
    const float* pwb  = (const float*)d_in[10];
    const float* f1w  = (const float*)d_in[11];
    const float* f1b  = (const float*)d_in[12];
    const float* f2w  = (const float*)d_in[13];
    const float* f2b  = (const float*)d_in[14];
    float* out = (float*)d_out;
    (void)in_sizes; (void)n_in; (void)out_size;

    k_prep_w<<<(Ll*Cc*Cc*9 + 255)/256, 256>>>(chw, cww, pww, chb, cwb, pwb);
    k_prep_trig<<<40, 256>>>();
    k_fc0<<<NTOT/256, 256>>>(x, fc0w, fc0b);

    for (int l = 0; l < Ll; l++) {
        int sel = l & 1;                              // 0: h0->h1, 1: h1->h0
        k_conv<<<dim3(8, 32, 8), 256>>>(l, sel);
        k_fwdx<<<BC*Hh/16, 512>>>(sel);
        k_fwdy<<<BC, 800>>>();
        k_mix<<<800, 512>>>(w1, w2, l);
        k_invy<<<BC, 640>>>();
        k_invx<<<dim3(BC, 16), 512>>>(sel, (l < Ll-1) ? 1 : 0);
    }
    // after 4 layers (even count), final h is in g_h0
    k_head<<<NPIX/256, 256>>>(f1w, f1b, f2w, f2b, out);
}

// round 11
// speedup vs baseline: 1.5971x; 1.0635x over previous
#include <cuda_runtime.h>
#include <math.h>

#define Bn 8
#define Cc 64
#define Hh 256
#define Ww 256
#define Ll 4
#define M1 20
#define M2 20
#define BC (Bn*Cc)          // 512
#define HW (Hh*Ww)          // 65536
#define NPIX (Bn*HW)        // 524288
#define NTOT (BC*HW)        // 33554432

// packed f32x2 FMA (sm_100+; only reachable via PTX — ptxas never auto-fuses)
#define FMA2(acc, a, b) \
    asm("fma.rn.f32x2 %0, %1, %2, %0;" : "+l"(acc) : "l"(a), "l"(b))
#define PACKF2(out, v) \
    asm("mov.b64 %0, {%1, %1};" : "=l"(out) : "r"(__float_as_uint(v)))

// cp.async (LDGSTS) helpers — no register staging, background copy
__device__ __forceinline__ void cp_async4(unsigned dst, const float* src, bool pred) {
    int sz = pred ? 4 : 0;                         // src-size 0 => zero-fill
    asm volatile("cp.async.ca.shared.global [%0], [%1], 4, %2;"
                 :: "r"(dst), "l"(src), "r"(sz));
}
__device__ __forceinline__ void cp_async16(unsigned dst, const float4* src) {
    asm volatile("cp.async.ca.shared.global [%0], [%1], 16;" :: "r"(dst), "l"(src));
}
#define CP_COMMIT() asm volatile("cp.async.commit_group;")
#define CP_WAIT0()  asm volatile("cp.async.wait_group 0;")

// ---------------- scratch (device globals; no allocations allowed) ----------
__device__ float g_h0[NTOT];                 // ping
__device__ float g_h1[NTOT];                 // pong
__device__ float g_xf[BC*Hh*M2*2];           // fwd-x result (bc,y,kx) complex
__device__ float g_F [BC*2*M1*M2*2];         // fwd-y result (bc,kyi,kx) complex
__device__ float g_D [BC*2*M1*M2*2];         // after channel mix
__device__ float g_gy[BC*Hh*M2*2];           // inv-y result (bc,y,kx) complex, pre-scaled
__device__ float g_wt[Ll*Cc*9*Cc];           // combined conv weights [l][ci][tap][co]
__device__ float g_bc2[Ll*Cc];               // combined conv bias
__device__ float g_wm[Ll*40*20*Cc*Cc*2];     // mode-contiguous mix weights [l][kyi][kx][i][o][2]
__device__ float g_cx[M2*Hh];                // cos(2pi k x/256), [k][x]
__device__ float g_sx[M2*Hh];                // sin(2pi k x/256), [k][x]
__device__ float g_cy[Hh*2*M1];              // [y][kyi], ky = kyi<20?kyi:216+kyi
__device__ float g_sy[Hh*2*M1];

// ---------------- prep: fold convh+convw+pw into one 3x3 conv ---------------
__global__ void k_prep_w(const float* __restrict__ ch, const float* __restrict__ cw,
                         const float* __restrict__ pw, const float* __restrict__ bh,
                         const float* __restrict__ bw, const float* __restrict__ bp)
{
    int idx = blockIdx.x*blockDim.x + threadIdx.x;
    int total = Ll*Cc*Cc*9;
    if (idx < total) {
        // destination layout: [l][ci][tap][co]  (co fastest -> co-pairs are contiguous)
        int co  = idx & 63;
        int tap = (idx >> 6) % 9;
        int ci  = (idx / (64*9)) & 63;
        int l   = idx / (64*9*64);
        int src = ((l*64 + co)*64 + ci)*9 + tap;       // source: (L,O,I,3,3)
        float v = ch[src] + cw[src];
        if (tap == 4) v += pw[(l*64 + co)*64 + ci];    // 1x1 folded into center
        g_wt[idx] = v;
    }
    if (idx < Ll*Cc) g_bc2[idx] = bh[idx] + bw[idx] + bp[idx];
}

// repack spectral weights to per-mode-contiguous layout (coalesced k_mix loads)
__global__ void k_prep_wmix(const float* __restrict__ w1, const float* __restrict__ w2)
{
    const size_t PER = (size_t)Ll*64*64*400;           // 6,553,600 complex elems
    size_t idx = (size_t)blockIdx.x*256 + threadIdx.x;
    if (idx >= 2*PER) return;
    int arr = idx >= PER;
    size_t s = arr ? idx - PER : idx;
    int kx = (int)(s % 20); s /= 20;
    int kk = (int)(s % 20); s /= 20;
    int o  = (int)(s % 64); s /= 64;
    int i  = (int)(s % 64); s /= 64;
    int l  = (int)s;
    const float* src = (arr ? w2 : w1) + ((((size_t)(l*64+i)*64+o)*20+kk)*20+kx)*2;
    int kyi = arr ? (20 + kk) : kk;
    float2 v = *(const float2*)src;
    *(float2*)&g_wm[((((size_t)(l*40+kyi)*20+kx)*64+i)*64+o)*2] = v;
}

__global__ void k_prep_trig()
{
    int idx = blockIdx.x*blockDim.x + threadIdx.x;
    if (idx < M2*Hh) {                                  // [k][x]
        int k = idx >> 8, x = idx & 255;
        int m = (k*x) & 255;                            // exact angle reduction
        double t = (double)m * (6.283185307179586476925287 / 256.0);
        double s, c; sincos(t, &s, &c);
        g_cx[idx] = (float)c; g_sx[idx] = (float)s;
    }
    if (idx < Hh*2*M1) {                                // [y][kyi]
        int y = idx / 40, kyi = idx % 40;
        int ky = (kyi < 20) ? kyi : (216 + kyi);        // 236..255
        int m = (ky*y) & 255;
        double t = (double)m * (6.283185307179586476925287 / 256.0);
        double s, c; sincos(t, &s, &c);
        g_cy[idx] = (float)c; g_sy[idx] = (float)s;
    }
}

// ---------------- fc0 lift: (B,H,W,3) -> (B,C,H,W) --------------------------
__global__ void k_fc0(const float* __restrict__ xin, const float* __restrict__ w,
                      const float* __restrict__ b)
{
    int idx = blockIdx.x*blockDim.x + threadIdx.x;
    if (idx >= NTOT) return;
    int x  = idx & 255;
    int y  = (idx >> 8) & 255;
    int c  = (idx >> 16) & 63;
    int bb = idx >> 22;
    const float* xp = xin + ((size_t)(bb*Hh + y)*Ww + x)*3;
    float v = __ldg(&b[c]) + xp[0]*__ldg(&w[c]) + xp[1]*__ldg(&w[64+c]) + xp[2]*__ldg(&w[128+c]);
    g_h0[idx] = v;
}

// ---------------- combined 3x3 conv (NCHW), f32x2 + cp.async pipeline -------
// Tile: 32x8 pixels, all 64 co. Thread = 8 consecutive x-pixels x 8 co.
// Double-buffered smem filled via cp.async (zero register staging): one sync
// per ci-chunk, LDG latency overlapped with the 288-FMA2 compute block.
__global__ __launch_bounds__(256, 2) void k_conv(int l, int sel)
{
    const float* hin = sel ? g_h1 : g_h0;
    float*      hout = sel ? g_h0 : g_h1;

    __shared__ float s_in[2][8][10][36];              // 2 x 11.25KB
    __shared__ __align__(16) float s_w[2][8*9*64];    // 2 x 18KB

    int t  = threadIdx.x;
    int cog = t & 7;                                  // co group: 8 co each
    int p   = t >> 3;                                 // 0..31 pixel group
    int px8 = (p & 3) * 8;                            // x offset within tile
    int py  = p >> 2;                                 // 0..7
    int x0 = blockIdx.x * 32;
    int y0 = blockIdx.y * 8;
    int b  = blockIdx.z;
    const float* hb = hin + (size_t)b*Cc*HW;

    auto issue = [&](int cc, int buf) {
        unsigned sin_b = (unsigned)__cvta_generic_to_shared(&s_in[buf][0][0][0]);
        unsigned sw_b  = (unsigned)__cvta_generic_to_shared(&s_w[buf][0]);
        for (int e = t; e < 8*10*34; e += 256) {
            int ci = e / 340;
            int r  = e % 340;
            int dy = r / 34, dx = r % 34;
            int gy = y0 + dy - 1, gx = x0 + dx - 1;
            bool ok = (gy >= 0 && gy < 256 && gx >= 0 && gx < 256);
            const float* src = ok ? &hb[(size_t)(cc*8 + ci)*HW + gy*256 + gx] : hb;
            cp_async4(sin_b + (unsigned)(((ci*10 + dy)*36 + dx)*4), src, ok);
        }
        const float4* wsrc = (const float4*)&g_wt[((l*64 + cc*8)*9)*64];
        for (int e = t; e < 8*9*16; e += 256)
            cp_async16(sw_b + (unsigned)(e*16), wsrc + e);
        CP_COMMIT();
    };

    // accp[pair][q]: pair = (co 2*pair, 2*pair+1) within this cog's 8 co, q = pixel
    unsigned long long accp[4][8];
#pragma unroll
    for (int i = 0; i < 4; i++)
#pragma unroll
        for (int q = 0; q < 8; q++) accp[i][q] = 0ULL;   // (0.f,0.f)

    issue(0, 0);
    for (int cc = 0; cc < 8; cc++) {
        int buf = cc & 1;
        CP_WAIT0();
        __syncthreads();
        if (cc < 7) issue(cc + 1, buf ^ 1);

#pragma unroll
        for (int ci = 0; ci < 8; ci++) {
#pragma unroll
            for (int fy = 0; fy < 3; fy++) {
                // 10-wide input window [px8 .. px8+9] for 8 pixels x 3 fx taps
                const float* rp = &s_in[buf][ci][py+fy][px8];
                float4 a4 = *(const float4*)rp;
                float4 b4 = *(const float4*)(rp + 4);
                float2 c2 = *(const float2*)(rp + 8);
                unsigned long long xs[10];
                PACKF2(xs[0], a4.x); PACKF2(xs[1], a4.y);
                PACKF2(xs[2], a4.z); PACKF2(xs[3], a4.w);
                PACKF2(xs[4], b4.x); PACKF2(xs[5], b4.y);
                PACKF2(xs[6], b4.z); PACKF2(xs[7], b4.w);
                PACKF2(xs[8], c2.x); PACKF2(xs[9], c2.y);
#pragma unroll
                for (int fx = 0; fx < 3; fx++) {
                    const ulonglong2* wp =
                        (const ulonglong2*)&s_w[buf][(ci*9 + fy*3 + fx)*64 + cog*8];
                    ulonglong2 w0 = wp[0];
                    ulonglong2 w1 = wp[1];
#pragma unroll
                    for (int q = 0; q < 8; q++) {
                        FMA2(accp[0][q], w0.x, xs[fx+q]);
                        FMA2(accp[1][q], w0.y, xs[fx+q]);
                        FMA2(accp[2][q], w1.x, xs[fx+q]);
                        FMA2(accp[3][q], w1.y, xs[fx+q]);
                    }
                }
            }
        }
    }

    float* ob = hout + (size_t)b*Cc*HW + (size_t)(y0+py)*256 + (x0+px8);
#pragma unroll
    for (int pr = 0; pr < 4; pr++) {
        int co0 = cog*8 + 2*pr;
        float b0 = __ldg(&g_bc2[l*64 + co0]);
        float b1 = __ldg(&g_bc2[l*64 + co0 + 1]);
        float2 q0 = *(float2*)&accp[pr][0];
        float2 q1 = *(float2*)&accp[pr][1];
        float2 q2 = *(float2*)&accp[pr][2];
        float2 q3 = *(float2*)&accp[pr][3];
        float2 q4 = *(float2*)&accp[pr][4];
        float2 q5 = *(float2*)&accp[pr][5];
        float2 q6 = *(float2*)&accp[pr][6];
        float2 q7 = *(float2*)&accp[pr][7];
        float* r0 = &ob[(size_t)co0*HW];
        float* r1 = &ob[(size_t)(co0+1)*HW];
        *(float4*)(r0    ) = make_float4(q0.x+b0, q1.x+b0, q2.x+b0, q3.x+b0);
        *(float4*)(r0 + 4) = make_float4(q4.x+b0, q5.x+b0, q6.x+b0, q7.x+b0);
        *(float4*)(r1    ) = make_float4(q0.y+b1, q1.y+b1, q2.y+b1, q3.y+b1);
        *(float4*)(r1 + 4) = make_float4(q4.y+b1, q5.y+b1, q6.y+b1, q7.y+b1);
    }
}

// ---------------- forward partial DFT along x: 20 modes ---------------------
// 64 rows per block: 40KB trig table load amortized 4x vs 16 rows/block.
__global__ __launch_bounds__(512) void k_fwdx(int sel)
{
    const float* hin = sel ? g_h1 : g_h0;
    __shared__ float sc[M2*Hh];
    __shared__ float ss[M2*Hh];
    int t = threadIdx.x;
    for (int e = t; e < M2*Hh; e += 512) { sc[e] = g_cx[e]; ss[e] = g_sx[e]; }
    __syncthreads();

    int warp = t >> 5, lane = t & 31;
    int row0 = blockIdx.x * 64 + warp * 4;            // 16 warps x 4 rows = 64 rows
    for (int rr = 0; rr < 4; rr++) {
        int row = row0 + rr;
        const float* rp = hin + (size_t)row * 256;
        float v[8];
#pragma unroll
        for (int j = 0; j < 8; j++) v[j] = rp[lane + 32*j];

        float* outp = g_xf + (size_t)row * (M2*2);
        for (int k = 0; k < 20; k++) {
            float ar = 0.f, ai = 0.f;
#pragma unroll
            for (int j = 0; j < 8; j++) {
                int x = lane + 32*j;
                float c = sc[k*256 + x], s = ss[k*256 + x];
                ar += v[j]*c;
                ai -= v[j]*s;
            }
#pragma unroll
            for (int o = 16; o > 0; o >>= 1) {
                ar += __shfl_xor_sync(0xffffffffu, ar, o);
                ai += __shfl_xor_sync(0xffffffffu, ai, o);
            }
            if (lane == 0) { outp[2*k] = ar*0.0625f; outp[2*k+1] = ai*0.0625f; }
        }
    }
}

// ---------------- forward partial DFT along y: 40 modes (0..19, 236..255) ---
__global__ __launch_bounds__(800) void k_fwdy()
{
    __shared__ float sX[Hh*M2*2];                     // 40KB slab for this image
    int bc = blockIdx.x;
    int t  = threadIdx.x;
    const float* src = g_xf + (size_t)bc * (Hh*M2*2);
    for (int e = t; e < Hh*M2*2; e += 800) sX[e] = src[e];
    __syncthreads();

    int kx = t % 20, kyi = t / 20;                    // kyi in [0,40)
    float ar = 0.f, ai = 0.f;
#pragma unroll 4
    for (int y = 0; y < 256; y++) {
        float xr = sX[(y*20 + kx)*2], xi = sX[(y*20 + kx)*2 + 1];
        float c = __ldg(&g_cy[y*40 + kyi]), s = __ldg(&g_sy[y*40 + kyi]);
        ar += xr*c + xi*s;                            // X * e^{-i th}
        ai += xi*c - xr*s;
    }
    size_t o = ((size_t)(bc*40 + kyi)*20 + kx)*2;
    g_F[o]   = ar*0.0625f;
    g_F[o+1] = ai*0.0625f;
}

// ---------------- per-mode 64x64 complex channel mix ------------------------
// Weights read from g_wm (mode-contiguous, coalesced float4 stream).
__global__ __launch_bounds__(512) void k_mix(int l)
{
    __shared__ __align__(16) float sW[Cc*Cc*2];       // [i][o] complex, 32KB
    __shared__ float sF[Bn*Cc*2];                     // [b][i] complex, 4KB
    int m   = blockIdx.x;                             // 0..799
    int kyi = m / 20, kx = m % 20;
    int t = threadIdx.x;

    {
        const float4* src4 = (const float4*)&g_wm[(size_t)(l*800 + m) * (Cc*Cc*2)];
        float4* dst4 = (float4*)sW;
        for (int e = t; e < Cc*Cc*2/4; e += 512) dst4[e] = src4[e];
    }
    {
        int e = t;                                    // e = b*64+i  (512 threads)
        size_t s = (((size_t)e*40 + kyi)*20 + kx)*2;
        sF[e*2]   = g_F[s];
        sF[e*2+1] = g_F[s+1];
    }
    __syncthreads();

    int o = t & 63, b = t >> 6;
    float ar = 0.f, ai = 0.f;
#pragma unroll 4
    for (int i = 0; i < 64; i++) {
        float fr = sF[(b*64 + i)*2], fi = sF[(b*64 + i)*2 + 1];
        float wr = sW[(i*64 + o)*2], wi = sW[(i*64 + o)*2 + 1];
        ar += fr*wr - fi*wi;
        ai += fr*wi + fi*wr;
    }
    size_t d = (((size_t)(b*64 + o)*40 + kyi)*20 + kx)*2;
    g_D[d] = ar; g_D[d+1] = ai;
}

// ---------------- inverse DFT along y (pre-scales for inv-x) ----------------
__global__ __launch_bounds__(640) void k_invy()
{
    __shared__ float sD[2*M1*M2*2];                   // 1600 floats
    int bc = blockIdx.x;
    int t  = threadIdx.x;
    const float* src = g_D + (size_t)bc*2*M1*M2*2;
    for (int e = t; e < 2*M1*M2*2; e += 640) sD[e] = src[e];
    __syncthreads();

    int kx = t % 20, yb = t / 20;                     // yb in [0,32)
    float scale = (kx == 0) ? (1.0f/256.0f) : (2.0f/256.0f);
    for (int jj = 0; jj < 8; jj++) {
        int y = yb + 32*jj;
        float ar = 0.f, ai = 0.f;
#pragma unroll 8
        for (int kyi = 0; kyi < 40; kyi++) {
            float dr = sD[(kyi*20 + kx)*2], di = sD[(kyi*20 + kx)*2 + 1];
            float c = __ldg(&g_cy[y*40 + kyi]), s = __ldg(&g_sy[y*40 + kyi]);
            ar += dr*c - di*s;                        // D * e^{+i th}
            ai += dr*s + di*c;
        }
        size_t o = ((size_t)(bc*256 + y)*20 + kx)*2;
        g_gy[o] = ar*scale; g_gy[o+1] = ai*scale;
    }
}

// ---------------- inverse DFT along x + add conv + GeLU ---------------------
// 64 y-rows per block: trig table load amortized 4x.
__global__ __launch_bounds__(512) void k_invx(int sel, int do_gelu)
{
    float* hout = sel ? g_h0 : g_h1;                  // conv output buffer
    __shared__ float sc[M2*Hh];
    __shared__ float ss[M2*Hh];
    __shared__ float sg[64][40];
    int t = threadIdx.x;
    for (int e = t; e < M2*Hh; e += 512) { sc[e] = g_cx[e]; ss[e] = g_sx[e]; }

    int bc = blockIdx.x;
    int y0 = blockIdx.y * 64;
    for (int e = t; e < 64*40; e += 512) {
        int r = e / 40, q = e % 40;
        sg[r][q] = g_gy[((size_t)(bc*256 + y0 + r))*40 + q];
    }
    __syncthreads();

    int x = t & 255, r0 = t >> 8;                     // r0 in {0,1}
    for (int it = 0; it < 32; it++) {
        int r = r0 + 2*it;
        float val = sg[r][0];                         // kx=0: Re only (C2R semantics)
#pragma unroll
        for (int k = 1; k < 20; k++) {
            float gr = sg[r][2*k], gi = sg[r][2*k+1];
            val += gr*sc[k*256 + x] - gi*ss[k*256 + x];
        }
        size_t idx = ((size_t)(bc*256 + y0 + r))*256 + x;
        float h = hout[idx] + val;
        if (do_gelu) h = 0.5f*h*(1.0f + erff(h*0.70710678118654752440f));
        hout[idx] = h;
    }
}

// ---------------- head: fc1 + gelu + fc2 ------------------------------------
__global__ __launch_bounds__(256) void k_head(const float* __restrict__ w1,
                                              const float* __restrict__ b1,
                                              const float* __restrict__ w2,
                                              const float* __restrict__ b2,
                                              float* __restrict__ out)
{
    __shared__ float sw1[64*128];
    __shared__ float sb1[128];
    __shared__ float sw2[128];
    int t = threadIdx.x;
    for (int e = t; e < 64*128; e += 256) sw1[e] = w1[e];
    if (t < 128) { sb1[t] = b1[t]; sw2[t] = w2[t]; }
    __syncthreads();

    int pix = blockIdx.x * 256 + t;                   // over NPIX
    int x = pix & 255, y = (pix >> 8) & 255, b = pix >> 16;
    const float* hp = g_h0 + (size_t)b*64*HW + (size_t)y*256 + x;  // final h in g_h0

    float o = __ldg(&b2[0]);
    for (int half = 0; half < 2; half++) {
        float acc[64];
#pragma unroll
        for (int d = 0; d < 64; d++) acc[d] = sb1[half*64 + d];
#pragma unroll 4
        for (int c = 0; c < 64; c++) {
            float v = __ldg(&hp[(size_t)c*HW]);
            const float4* wp = (const float4*)&sw1[c*128 + half*64];
#pragma unroll
            for (int j = 0; j < 16; j++) {
                float4 w4 = wp[j];
                acc[4*j+0] += v*w4.x;
                acc[4*j+1] += v*w4.y;
                acc[4*j+2] += v*w4.z;
                acc[4*j+3] += v*w4.w;
            }
        }
#pragma unroll
        for (int d = 0; d < 64; d++) {
            float tt = acc[d];
            tt = 0.5f*tt*(1.0f + erff(tt*0.70710678118654752440f));
            o += tt * sw2[half*64 + d];
        }
    }
    out[pix] = o;
}

// ---------------- launch -----------------------------------------------------
extern "C" void kernel_launch(void* const* d_in, const int* in_sizes, int n_in,
                              void* d_out, int out_size)
{
    const float* x    = (const float*)d_in[0];
    const float* fc0w = (const float*)d_in[1];
    const float* fc0b = (const float*)d_in[2];
    const float* w1   = (const float*)d_in[3];
    const float* w2   = (const float*)d_in[4];
    const float* chw  = (const float*)d_in[5];
    const float* chb  = (const float*)d_in[6];
    const float* cww  = (const float*)d_in[7];
    const float* cwb  = (const float*)d_in[8];
    const float* pww  = (const float*)d_in[9];
    const float* pwb  = (const float*)d_in[10];
    const float* f1w  = (const float*)d_in[11];
    const float* f1b  = (const float*)d_in[12];
    const float* f2w  = (const float*)d_in[13];
    const float* f2b  = (const float*)d_in[14];
    float* out = (float*)d_out;
    (void)in_sizes; (void)n_in; (void)out_size;

    k_prep_w<<<(Ll*Cc*Cc*9 + 255)/256, 256>>>(chw, cww, pww, chb, cwb, pwb);
    k_prep_wmix<<<(2*Ll*64*64*400 + 255)/256, 256>>>(w1, w2);
    k_prep_trig<<<40, 256>>>();
    k_fc0<<<NTOT/256, 256>>>(x, fc0w, fc0b);

    for (int l = 0; l < Ll; l++) {
        int sel = l & 1;                              // 0: h0->h1, 1: h1->h0
        k_conv<<<dim3(8, 32, 8), 256>>>(l, sel);
        k_fwdx<<<BC*Hh/64, 512>>>(sel);
        k_fwdy<<<BC, 800>>>();
        k_mix<<<800, 512>>>(l);
        k_invy<<<BC, 640>>>();
        k_invx<<<dim3(BC, 4), 512>>>(sel, (l < Ll-1) ? 1 : 0);
    }
    // after 4 layers (even count), final h is in g_h0
    k_head<<<NPIX/256, 256>>>(f1w, f1b, f2w, f2b, out);
}

// round 13
// speedup vs baseline: 1.6433x; 1.0289x over previous
#include <cuda_runtime.h>
#include <math.h>

#define Bn 8
#define Cc 64
#define Hh 256
#define Ww 256
#define Ll 4
#define M1 20
#define M2 20
#define BC (Bn*Cc)          // 512
#define HW (Hh*Ww)          // 65536
#define NPIX (Bn*HW)        // 524288
#define NTOT (BC*HW)        // 33554432

// packed f32x2 ops (sm_100+; only reachable via PTX — ptxas never auto-fuses)
#define FMA2(acc, a, b) \
    asm("fma.rn.f32x2 %0, %1, %2, %0;" : "+l"(acc) : "l"(a), "l"(b))
#define ADDF2(a, b) \
    asm("add.rn.f32x2 %0, %0, %1;" : "+l"(a) : "l"(b))
#define PACKF2(out, v) \
    asm("mov.b64 %0, {%1, %1};" : "=l"(out) : "r"(__float_as_uint(v)))

// cp.async (LDGSTS) helpers — no register staging, background copy
__device__ __forceinline__ void cp_async4(unsigned dst, const float* src, bool pred) {
    int sz = pred ? 4 : 0;                         // src-size 0 => zero-fill
    asm volatile("cp.async.ca.shared.global [%0], [%1], 4, %2;"
                 :: "r"(dst), "l"(src), "r"(sz));
}
__device__ __forceinline__ void cp_async16(unsigned dst, const float4* src) {
    asm volatile("cp.async.ca.shared.global [%0], [%1], 16;" :: "r"(dst), "l"(src));
}
#define CP_COMMIT() asm volatile("cp.async.commit_group;")
#define CP_WAIT0()  asm volatile("cp.async.wait_group 0;")

// ---------------- scratch (device globals; no allocations allowed) ----------
__device__ float g_h0[NTOT];                 // ping
__device__ float g_h1[NTOT];                 // pong
__device__ float g_xf[BC*Hh*M2*2];           // fwd-x result (bc,y,kx) complex
__device__ float g_F [BC*2*M1*M2*2];         // fwd-y result (bc,kyi,kx) complex
__device__ float g_D [BC*2*M1*M2*2];         // after channel mix
__device__ float g_gy[BC*Hh*M2*2];           // inv-y result (bc,y,kx) complex, pre-scaled
__device__ float g_wt[Ll*Cc*9*Cc];           // combined conv weights [l][ci][tap][co]
__device__ float g_bc2[Ll*Cc];               // combined conv bias
__device__ float g_wm[Ll*40*20*Cc*Cc*2];     // mode-contiguous mix weights [l][kyi][kx][i][o][2]
__device__ float g_cx[M2*Hh];                // cos(2pi k x/256), [k][x]
__device__ float g_sx[M2*Hh];                // sin(2pi k x/256), [k][x]
__device__ float g_cx2[10*Hh*2];             // paired cos: [kp][x][{2kp, 2kp+1}]
__device__ float g_sx2[10*Hh*2];             // paired sin
__device__ float g_cy[Hh*2*M1];              // [y][kyi], ky = kyi<20?kyi:216+kyi
__device__ float g_sy[Hh*2*M1];

// ---------------- prep: fold convh+convw+pw into one 3x3 conv ---------------
__global__ void k_prep_w(const float* __restrict__ ch, const float* __restrict__ cw,
                         const float* __restrict__ pw, const float* __restrict__ bh,
                         const float* __restrict__ bw, const float* __restrict__ bp)
{
    int idx = blockIdx.x*blockDim.x + threadIdx.x;
    int total = Ll*Cc*Cc*9;
    if (idx < total) {
        // destination layout: [l][ci][tap][co]  (co fastest -> co-pairs are contiguous)
        int co  = idx & 63;
        int tap = (idx >> 6) % 9;
        int ci  = (idx / (64*9)) & 63;
        int l   = idx / (64*9*64);
        int src = ((l*64 + co)*64 + ci)*9 + tap;       // source: (L,O,I,3,3)
        float v = ch[src] + cw[src];
        if (tap == 4) v += pw[(l*64 + co)*64 + ci];    // 1x1 folded into center
        g_wt[idx] = v;
    }
    if (idx < Ll*Cc) g_bc2[idx] = bh[idx] + bw[idx] + bp[idx];
}

// repack spectral weights to per-mode-contiguous layout (coalesced k_mix loads)
__global__ void k_prep_wmix(const float* __restrict__ w1, const float* __restrict__ w2)
{
    const size_t PER = (size_t)Ll*64*64*400;           // 6,553,600 complex elems
    size_t idx = (size_t)blockIdx.x*256 + threadIdx.x;
    if (idx >= 2*PER) return;
    int arr = idx >= PER;
    size_t s = arr ? idx - PER : idx;
    int kx = (int)(s % 20); s /= 20;
    int kk = (int)(s % 20); s /= 20;
    int o  = (int)(s % 64); s /= 64;
    int i  = (int)(s % 64); s /= 64;
    int l  = (int)s;
    const float* src = (arr ? w2 : w1) + ((((size_t)(l*64+i)*64+o)*20+kk)*20+kx)*2;
    int kyi = arr ? (20 + kk) : kk;
    float2 v = *(const float2*)src;
    *(float2*)&g_wm[((((size_t)(l*40+kyi)*20+kx)*64+i)*64+o)*2] = v;
}

__global__ void k_prep_trig()
{
    int idx = blockIdx.x*blockDim.x + threadIdx.x;
    if (idx < M2*Hh) {                                  // [k][x]
        int k = idx >> 8, x = idx & 255;
        int m = (k*x) & 255;                            // exact angle reduction
        double t = (double)m * (6.283185307179586476925287 / 256.0);
        double s, c; sincos(t, &s, &c);
        g_cx[idx] = (float)c; g_sx[idx] = (float)s;
    }
    if (idx < 10*Hh) {                                  // paired [kp][x] (k=2kp, 2kp+1)
        int kp = idx >> 8, x = idx & 255;
        int m0 = ((2*kp)*x) & 255;
        int m1 = ((2*kp+1)*x) & 255;
        double t0 = (double)m0 * (6.283185307179586476925287 / 256.0);
        double t1 = (double)m1 * (6.283185307179586476925287 / 256.0);
        double s0, c0, s1, c1; sincos(t0, &s0, &c0); sincos(t1, &s1, &c1);
        g_cx2[idx*2]   = (float)c0; g_cx2[idx*2+1] = (float)c1;
        g_sx2[idx*2]   = (float)s0; g_sx2[idx*2+1] = (float)s1;
    }
    if (idx < Hh*2*M1) {                                // [y][kyi]
        int y = idx / 40, kyi = idx % 40;
        int ky = (kyi < 20) ? kyi : (216 + kyi);        // 236..255
        int m = (ky*y) & 255;
        double t = (double)m * (6.283185307179586476925287 / 256.0);
        double s, c; sincos(t, &s, &c);
        g_cy[idx] = (float)c; g_sy[idx] = (float)s;
    }
}

// ---------------- fc0 lift: (B,H,W,3) -> (B,C,H,W), float4 ------------------
__global__ void k_fc0(const float* __restrict__ xin, const float* __restrict__ w,
                      const float* __restrict__ b)
{
    int i4 = blockIdx.x*blockDim.x + threadIdx.x;       // over NTOT/4
    if (i4 >= NTOT/4) return;
    int x4 = (i4 & 63) * 4;
    int y  = (i4 >> 6) & 255;
    int c  = (i4 >> 14) & 63;
    int bb = i4 >> 20;
    const float* xp = xin + ((size_t)(bb*Hh + y)*Ww + x4)*3;
    float w0 = __ldg(&w[c]), w1 = __ldg(&w[64+c]), w2 = __ldg(&w[128+c]);
    float bs = __ldg(&b[c]);
    float4 r;
    r.x = bs + xp[0]*w0 + xp[1] *w1 + xp[2] *w2;
    r.y = bs + xp[3]*w0 + xp[4] *w1 + xp[5] *w2;
    r.z = bs + xp[6]*w0 + xp[7] *w1 + xp[8] *w2;
    r.w = bs + xp[9]*w0 + xp[10]*w1 + xp[11]*w2;
    *(float4*)&g_h0[(size_t)i4*4] = r;
}

// ---------------- combined 3x3 conv (NCHW), f32x2 + cp.async pipeline -------
__global__ __launch_bounds__(256, 2) void k_conv(int l, int sel)
{
    const float* hin = sel ? g_h1 : g_h0;
    float*      hout = sel ? g_h0 : g_h1;

    __shared__ float s_in[2][8][10][36];              // 2 x 11.25KB
    __shared__ __align__(16) float s_w[2][8*9*64];    // 2 x 18KB

    int t  = threadIdx.x;
    int cog = t & 7;                                  // co group: 8 co each
    int p   = t >> 3;                                 // 0..31 pixel group
    int px8 = (p & 3) * 8;                            // x offset within tile
    int py  = p >> 2;                                 // 0..7
    int x0 = blockIdx.x * 32;
    int y0 = blockIdx.y * 8;
    int b  = blockIdx.z;
    const float* hb = hin + (size_t)b*Cc*HW;

    auto issue = [&](int cc, int buf) {
        unsigned sin_b = (unsigned)__cvta_generic_to_shared(&s_in[buf][0][0][0]);
        unsigned sw_b  = (unsigned)__cvta_generic_to_shared(&s_w[buf][0]);
        for (int e = t; e < 8*10*34; e += 256) {
            int ci = e / 340;
            int r  = e % 340;
            int dy = r / 34, dx = r % 34;
            int gy = y0 + dy - 1, gx = x0 + dx - 1;
            bool ok = (gy >= 0 && gy < 256 && gx >= 0 && gx < 256);
            const float* src = ok ? &hb[(size_t)(cc*8 + ci)*HW + gy*256 + gx] : hb;
            cp_async4(sin_b + (unsigned)(((ci*10 + dy)*36 + dx)*4), src, ok);
        }
        const float4* wsrc = (const float4*)&g_wt[((l*64 + cc*8)*9)*64];
        for (int e = t; e < 8*9*16; e += 256)
            cp_async16(sw_b + (unsigned)(e*16), wsrc + e);
        CP_COMMIT();
    };

    unsigned long long accp[4][8];
#pragma unroll
    for (int i = 0; i < 4; i++)
#pragma unroll
        for (int q = 0; q < 8; q++) accp[i][q] = 0ULL;   // (0.f,0.f)

    issue(0, 0);
    for (int cc = 0; cc < 8; cc++) {
        int buf = cc & 1;
        CP_WAIT0();
        __syncthreads();
        if (cc < 7) issue(cc + 1, buf ^ 1);

#pragma unroll
        for (int ci = 0; ci < 8; ci++) {
#pragma unroll
            for (int fy = 0; fy < 3; fy++) {
                const float* rp = &s_in[buf][ci][py+fy][px8];
                float4 a4 = *(const float4*)rp;
                float4 b4 = *(const float4*)(rp + 4);
                float2 c2 = *(const float2*)(rp + 8);
                unsigned long long xs[10];
                PACKF2(xs[0], a4.x); PACKF2(xs[1], a4.y);
                PACKF2(xs[2], a4.z); PACKF2(xs[3], a4.w);
                PACKF2(xs[4], b4.x); PACKF2(xs[5], b4.y);
                PACKF2(xs[6], b4.z); PACKF2(xs[7], b4.w);
                PACKF2(xs[8], c2.x); PACKF2(xs[9], c2.y);
#pragma unroll
                for (int fx = 0; fx < 3; fx++) {
                    const ulonglong2* wp =
                        (const ulonglong2*)&s_w[buf][(ci*9 + fy*3 + fx)*64 + cog*8];
                    ulonglong2 w0 = wp[0];
                    ulonglong2 w1 = wp[1];
#pragma unroll
                    for (int q = 0; q < 8; q++) {
                        FMA2(accp[0][q], w0.x, xs[fx+q]);
                        FMA2(accp[1][q], w0.y, xs[fx+q]);
                        FMA2(accp[2][q], w1.x, xs[fx+q]);
                        FMA2(accp[3][q], w1.y, xs[fx+q]);
                    }
                }
            }
        }
    }

    float* ob = hout + (size_t)b*Cc*HW + (size_t)(y0+py)*256 + (x0+px8);
#pragma unroll
    for (int pr = 0; pr < 4; pr++) {
        int co0 = cog*8 + 2*pr;
        float b0 = __ldg(&g_bc2[l*64 + co0]);
        float b1 = __ldg(&g_bc2[l*64 + co0 + 1]);
        float2 q0 = *(float2*)&accp[pr][0];
        float2 q1 = *(float2*)&accp[pr][1];
        float2 q2 = *(float2*)&accp[pr][2];
        float2 q3 = *(float2*)&accp[pr][3];
        float2 q4 = *(float2*)&accp[pr][4];
        float2 q5 = *(float2*)&accp[pr][5];
        float2 q6 = *(float2*)&accp[pr][6];
        float2 q7 = *(float2*)&accp[pr][7];
        float* r0 = &ob[(size_t)co0*HW];
        float* r1 = &ob[(size_t)(co0+1)*HW];
        *(float4*)(r0    ) = make_float4(q0.x+b0, q1.x+b0, q2.x+b0, q3.x+b0);
        *(float4*)(r0 + 4) = make_float4(q4.x+b0, q5.x+b0, q6.x+b0, q7.x+b0);
        *(float4*)(r1    ) = make_float4(q0.y+b1, q1.y+b1, q2.y+b1, q3.y+b1);
        *(float4*)(r1 + 4) = make_float4(q4.y+b1, q5.y+b1, q6.y+b1, q7.y+b1);
    }
}

// ---------------- forward partial DFT along x: 20 modes, k-paired f32x2 -----
__global__ __launch_bounds__(512) void k_fwdx(int sel)
{
    const float* hin = sel ? g_h1 : g_h0;
    __shared__ __align__(8) float sc2[10*Hh*2];
    __shared__ __align__(8) float ss2[10*Hh*2];
    int t = threadIdx.x;
    for (int e = t; e < 10*Hh*2; e += 512) { sc2[e] = g_cx2[e]; ss2[e] = g_sx2[e]; }
    __syncthreads();

    int warp = t >> 5, lane = t & 31;
    int row0 = blockIdx.x * 64 + warp * 4;            // 16 warps x 4 rows
    for (int rr = 0; rr < 4; rr++) {
        int row = row0 + rr;
        const float* rp = hin + (size_t)row * 256;
        unsigned long long vs[8];
#pragma unroll
        for (int j = 0; j < 8; j++) { float v = rp[lane + 32*j]; PACKF2(vs[j], v); }

        float* outp = g_xf + (size_t)row * (M2*2);
        for (int kp = 0; kp < 10; kp++) {
            unsigned long long ar = 0ULL, ai = 0ULL;
#pragma unroll
            for (int j = 0; j < 8; j++) {
                int x = lane + 32*j;
                unsigned long long c2 = *(const unsigned long long*)&sc2[(kp*256 + x)*2];
                unsigned long long s2 = *(const unsigned long long*)&ss2[(kp*256 + x)*2];
                FMA2(ar, vs[j], c2);
                FMA2(ai, vs[j], s2);
            }
#pragma unroll
            for (int o = 16; o > 0; o >>= 1) {
                unsigned long long t1 = __shfl_xor_sync(0xffffffffu, ar, o);
                unsigned long long t2 = __shfl_xor_sync(0xffffffffu, ai, o);
                ADDF2(ar, t1);
                ADDF2(ai, t2);
            }
            if (lane == 0) {
                float2 arf = *(float2*)&ar;
                float2 aif = *(float2*)&ai;
                outp[4*kp+0] =  arf.x*0.0625f;
                outp[4*kp+1] = -(aif.x*0.0625f);
                outp[4*kp+2] =  arf.y*0.0625f;
                outp[4*kp+3] = -(aif.y*0.0625f);
            }
        }
    }
}

// ---------------- forward partial DFT along y: 40 modes (0..19, 236..255) ---
__global__ __launch_bounds__(800) void k_fwdy()
{
    __shared__ float sX[Hh*M2*2];                     // 40KB slab for this image
    int bc = blockIdx.x;
    int t  = threadIdx.x;
    const float* src = g_xf + (size_t)bc * (Hh*M2*2);
    for (int e = t; e < Hh*M2*2; e += 800) sX[e] = src[e];
    __syncthreads();

    int kx = t % 20, kyi = t / 20;                    // kyi in [0,40)
    float ar = 0.f, ai = 0.f;
#pragma unroll 4
    for (int y = 0; y < 256; y++) {
        float xr = sX[(y*20 + kx)*2], xi = sX[(y*20 + kx)*2 + 1];
        float c = __ldg(&g_cy[y*40 + kyi]), s = __ldg(&g_sy[y*40 + kyi]);
        ar += xr*c + xi*s;                            // X * e^{-i th}
        ai += xi*c - xr*s;
    }
    size_t o = ((size_t)(bc*40 + kyi)*20 + kx)*2;
    g_F[o]   = ar*0.0625f;
    g_F[o+1] = ai*0.0625f;
}

// ---------------- per-mode 64x64 complex channel mix ------------------------
__global__ __launch_bounds__(512) void k_mix(int l)
{
    __shared__ __align__(16) float sW[Cc*Cc*2];       // [i][o] complex, 32KB
    __shared__ float sF[Bn*Cc*2];                     // [b][i] complex, 4KB
    int m   = blockIdx.x;                             // 0..799
    int kyi = m / 20, kx = m % 20;
    int t = threadIdx.x;

    {
        const float4* src4 = (const float4*)&g_wm[(size_t)(l*800 + m) * (Cc*Cc*2)];
        float4* dst4 = (float4*)sW;
        for (int e = t; e < Cc*Cc*2/4; e += 512) dst4[e] = src4[e];
    }
    {
        int e = t;                                    // e = b*64+i  (512 threads)
        size_t s = (((size_t)e*40 + kyi)*20 + kx)*2;
        sF[e*2]   = g_F[s];
        sF[e*2+1] = g_F[s+1];
    }
    __syncthreads();

    int o = t & 63, b = t >> 6;
    float ar = 0.f, ai = 0.f;
#pragma unroll 4
    for (int i = 0; i < 64; i++) {
        float fr = sF[(b*64 + i)*2], fi = sF[(b*64 + i)*2 + 1];
        float wr = sW[(i*64 + o)*2], wi = sW[(i*64 + o)*2 + 1];
        ar += fr*wr - fi*wi;
        ai += fr*wi + fi*wr;
    }
    size_t d = (((size_t)(b*64 + o)*40 + kyi)*20 + kx)*2;
    g_D[d] = ar; g_D[d+1] = ai;
}

// ---------------- inverse DFT along y (pre-scales for inv-x) ----------------
__global__ __launch_bounds__(640) void k_invy()
{
    __shared__ float sD[2*M1*M2*2];                   // 1600 floats
    int bc = blockIdx.x;
    int t  = threadIdx.x;
    const float* src = g_D + (size_t)bc*2*M1*M2*2;
    for (int e = t; e < 2*M1*M2*2; e += 640) sD[e] = src[e];
    __syncthreads();

    int kx = t % 20, yb = t / 20;                     // yb in [0,32)
    float scale = (kx == 0) ? (1.0f/256.0f) : (2.0f/256.0f);
    for (int jj = 0; jj < 8; jj++) {
        int y = yb + 32*jj;
        float ar = 0.f, ai = 0.f;
#pragma unroll 8
        for (int kyi = 0; kyi < 40; kyi++) {
            float dr = sD[(kyi*20 + kx)*2], di = sD[(kyi*20 + kx)*2 + 1];
            float c = __ldg(&g_cy[y*40 + kyi]), s = __ldg(&g_sy[y*40 + kyi]);
            ar += dr*c - di*s;                        // D * e^{+i th}
            ai += dr*s + di*c;
        }
        size_t o = ((size_t)(bc*256 + y)*20 + kx)*2;
        g_gy[o] = ar*scale; g_gy[o+1] = ai*scale;
    }
}

// ---------------- inverse DFT along x + add conv + GeLU, x-paired f32x2 -----
__global__ __launch_bounds__(512) void k_invx(int sel, int do_gelu)
{
    float* hout = sel ? g_h0 : g_h1;                  // conv output buffer
    __shared__ __align__(8) float sc[M2*Hh];
    __shared__ __align__(8) float ss[M2*Hh];
    __shared__ float sg[64][40];
    int t = threadIdx.x;
    for (int e = t; e < M2*Hh; e += 512) { sc[e] = g_cx[e]; ss[e] = g_sx[e]; }

    int bc = blockIdx.x;
    int y0 = blockIdx.y * 64;
    for (int e = t; e < 64*40; e += 512) {
        sg[e/40][e%40] = g_gy[((size_t)(bc*256 + y0 + e/40))*40 + e%40];
    }
    __syncthreads();

    int x  = (t & 127) * 2;                           // x pair (x, x+1)
    int r0 = t >> 7;                                  // 0..3
    for (int it = 0; it < 16; it++) {
        int r = r0 + 4*it;
        unsigned long long val;
        PACKF2(val, sg[r][0]);                        // kx=0: Re only (C2R semantics)
#pragma unroll
        for (int k = 1; k < 20; k++) {
            unsigned long long gr2, gn2;
            float grv = sg[r][2*k], giv = sg[r][2*k+1];
            PACKF2(gr2, grv);
            PACKF2(gn2, -giv);
            unsigned long long c2 = *(const unsigned long long*)&sc[k*256 + x];
            unsigned long long s2 = *(const unsigned long long*)&ss[k*256 + x];
            FMA2(val, gr2, c2);                       // += gr*c
            FMA2(val, gn2, s2);                       // -= gi*s
        }
        size_t idx = ((size_t)(bc*256 + y0 + r))*256 + x;
        float2 h2 = *(float2*)&hout[idx];
        float2 vf = *(float2*)&val;
        float h0v = h2.x + vf.x, h1v = h2.y + vf.y;
        if (do_gelu) {
            h0v = 0.5f*h0v*(1.0f + erff(h0v*0.70710678118654752440f));
            h1v = 0.5f*h1v*(1.0f + erff(h1v*0.70710678118654752440f));
        }
        *(float2*)&hout[idx] = make_float2(h0v, h1v);
    }
}

// ---------------- head: fc1 + gelu + fc2, d-paired f32x2 --------------------
__global__ __launch_bounds__(256) void k_head(const float* __restrict__ w1,
                                              const float* __restrict__ b1,
                                              const float* __restrict__ w2,
                                              const float* __restrict__ b2,
                                              float* __restrict__ out)
{
    __shared__ __align__(16) float sw1[64*128];
    __shared__ __align__(8)  float sb1[128];
    __shared__ float sw2[128];
    int t = threadIdx.x;
    for (int e = t; e < 64*128; e += 256) sw1[e] = w1[e];
    if (t < 128) { sb1[t] = b1[t]; sw2[t] = w2[t]; }
    __syncthreads();

    int pix = blockIdx.x * 256 + t;                   // over NPIX
    int x = pix & 255, y = (pix >> 8) & 255, b = pix >> 16;
    const float* hp = g_h0 + (size_t)b*64*HW + (size_t)y*256 + x;  // final h in g_h0

    float o = __ldg(&b2[0]);
    for (int half = 0; half < 2; half++) {
        unsigned long long acc[32];                   // (d, d+1) pairs, 64 d per half
#pragma unroll
        for (int dp = 0; dp < 32; dp++)
            acc[dp] = *(const unsigned long long*)&sb1[half*64 + 2*dp];
#pragma unroll 4
        for (int c = 0; c < 64; c++) {
            unsigned long long vv;
            PACKF2(vv, __ldg(&hp[(size_t)c*HW]));
            const ulonglong2* wp = (const ulonglong2*)&sw1[c*128 + half*64];
#pragma unroll
            for (int j = 0; j < 16; j++) {
                ulonglong2 w2p = wp[j];
                FMA2(acc[2*j],   vv, w2p.x);
                FMA2(acc[2*j+1], vv, w2p.y);
            }
        }
#pragma unroll
        for (int dp = 0; dp < 32; dp++) {
            float2 q = *(float2*)&acc[dp];
            float t0 = 0.5f*q.x*(1.0f + erff(q.x*0.70710678118654752440f));
            float t1 = 0.5f*q.y*(1.0f + erff(q.y*0.70710678118654752440f));
            o += t0 * sw2[half*64 + 2*dp];
            o += t1 * sw2[half*64 + 2*dp + 1];
        }
    }
    out[pix] = o;
}

// ---------------- launch -----------------------------------------------------
extern "C" void kernel_launch(void* const* d_in, const int* in_sizes, int n_in,
                              void* d_out, int out_size)
{
    const float* x    = (const float*)d_in[0];
    const float* fc0w = (const float*)d_in[1];
    const float* fc0b = (const float*)d_in[2];
    const float* w1   = (const float*)d_in[3];
    const float* w2   = (const float*)d_in[4];
    const float* chw  = (const float*)d_in[5];
    const float* chb  = (const float*)d_in[6];
    const float* cww  = (const float*)d_in[7];
    const float* cwb  = (const float*)d_in[8];
    const float* pww  = (const float*)d_in[9];
    const float* pwb  = (const float*)d_in[10];
    const float* f1w  = (const float*)d_in[11];
    const float* f1b  = (const float*)d_in[12];
    const float* f2w  = (const float*)d_in[13];
    const float* f2b  = (const float*)d_in[14];
    float* out = (float*)d_out;
    (void)in_sizes; (void)n_in; (void)out_size;

    k_prep_w<<<(Ll*Cc*Cc*9 + 255)/256, 256>>>(chw, cww, pww, chb, cwb, pwb);
    k_prep_wmix<<<(2*Ll*64*64*400 + 255)/256, 256>>>(w1, w2);
    k_prep_trig<<<40, 256>>>();
    k_fc0<<<NTOT/4/256, 256>>>(x, fc0w, fc0b);

    for (int l = 0; l < Ll; l++) {
        int sel = l & 1;                              // 0: h0->h1, 1: h1->h0
        k_conv<<<dim3(8, 32, 8), 256>>>(l, sel);
        k_fwdx<<<BC*Hh/64, 512>>>(sel);
        k_fwdy<<<BC, 800>>>();
        k_mix<<<800, 512>>>(l);
        k_invy<<<BC, 640>>>();
        k_invx<<<dim3(BC, 4), 512>>>(sel, (l < Ll-1) ? 1 : 0);
    }
    // after 4 layers (even count), final h is in g_h0
    k_head<<<NPIX/256, 256>>>(f1w, f1b, f2w, f2b, out);
}